// round 8
// baseline (speedup 1.0000x reference)
#include <cuda_runtime.h>
#include <cstdint>
#include <cstddef>

// ---------------- problem dims ----------------
#define HD    512
#define BATCH 1024
#define TSEQ  512
#define PLEN  96
#define DIN   32

// ---------------- tiling ----------------
#define NCTA 128
#define MT   8
#define NTL  16

#define A_TB 16384              // A tile: 128 rows x 128B ([limb1 64B | limb2 64B])
#define B_TB 12288              // B tile:  96 rows x 128B
#define BUF_BYTES (A_TB + B_TB) // 28672
#define SM_TOTAL  (2*BUF_BYTES) // 57344

// ---------------- device globals ----------------
__device__ float g_h1[2][BATCH*HD];
__device__ float g_h2[2][BATCH*HD];
__device__ __align__(16) signed char g_h1q[2][MT][8][A_TB];
__device__ __align__(16) signed char g_h2q[2][MT][8][A_TB];
__device__ __align__(16) signed char g_xq[TSEQ][MT][A_TB];   // [x1 32B | x2 32B | 0]
__device__ __align__(16) signed char g_wq[6][NTL][8][B_TB];  // 0:e0hh 1:e1ih 2:e1hh 3:d0hh 4:d1ih 5:d1hh
__device__ __align__(16) signed char g_wxq[NTL][B_TB];       // enc0 Wih: [w1 32B | w2 32B | 0]
__device__ float g_br[4][HD], g_bz[4][HD], g_bin[4][HD], g_bhn[4][HD];
__device__ float g_scale[4];    // per-bt hidden/input shared product scale qW (x 1, /128 for MID)
__device__ float g_sx[2];       // x-chunk scales: HI, MID
__device__ float g_y[BATCH];
__device__ unsigned g_fmax[5];  // family maxabs (bits)
__device__ unsigned g_cnt, g_gen;

// ---------------- addressing: 128B rows, 16B-unit XOR swizzle ----------------
__device__ __forceinline__ int offb(int r, int b) {
    return r * 128 + ((((b >> 4) ^ (r & 7)) << 4) | (b & 15));
}

// ---------------- PTX helpers ----------------
__device__ __forceinline__ uint32_t smem_u32(const void* p) {
    uint32_t a;
    asm("{ .reg .u64 t; cvta.to.shared.u64 t, %1; cvt.u32.u64 %0, t; }" : "=r"(a) : "l"(p));
    return a;
}
#define LDSM4(r, addr) asm volatile("ldmatrix.sync.aligned.m8n8.x4.shared.b16 {%0,%1,%2,%3},[%4];" \
    : "=r"((r)[0]), "=r"((r)[1]), "=r"((r)[2]), "=r"((r)[3]) : "r"(addr))
#define MMAI(d, a, b0, b1) asm volatile( \
    "mma.sync.aligned.m16n8k32.row.col.s32.s8.s8.s32 {%0,%1,%2,%3},{%4,%5,%6,%7},{%8,%9},{%0,%1,%2,%3};" \
    : "+r"((d)[0]), "+r"((d)[1]), "+r"((d)[2]), "+r"((d)[3]) \
    : "r"((a)[0]), "r"((a)[1]), "r"((a)[2]), "r"((a)[3]), "r"(b0), "r"(b1))
#define CPA16(sa, gp) asm volatile("cp.async.cg.shared.global [%0],[%1],16;" :: "r"(sa), "l"(gp))
#define CPCOMMIT()    asm volatile("cp.async.commit_group;" ::: "memory")
#define CPWAIT1()     asm volatile("cp.async.wait_group 1;" ::: "memory")
#define CPWAIT0()     asm volatile("cp.async.wait_group 0;" ::: "memory")

__device__ __forceinline__ int clamp127(float v) {
    int x = __float2int_rn(v);
    return x > 127 ? 127 : (x < -127 ? -127 : x);
}

// ---------------- init kernels ----------------
__global__ void k_reset() {
    if (threadIdx.x < 5) g_fmax[threadIdx.x] = 0u;
}

__global__ void k_maxw(const float* eWhh0, const float* eWih1, const float* eWhh1,
                       const float* dWhh0, const float* dWih1, const float* dWhh1,
                       const float* eWih0)
{
    const float* m[7] = {eWhh0, eWih1, eWhh1, dWhh0, dWih1, dWhh1, eWih0};
    const int fam[7] = {0, 1, 1, 2, 3, 3, 4};
    const long stride = (long)gridDim.x * blockDim.x;
    const long i0 = (long)blockIdx.x * blockDim.x + threadIdx.x;
    for (int s = 0; s < 7; s++) {
        const long sz = (s < 6) ? (long)3 * HD * HD : (long)3 * HD * DIN;
        float mx = 0.f;
        for (long i = i0; i < sz; i += stride) mx = fmaxf(mx, fabsf(m[s][i]));
        atomicMax(&g_fmax[fam[s]], __float_as_uint(mx));
    }
}

__global__ void k_quant(
    const float* eWih0,
    const float* eWhh0, const float* eWih1, const float* eWhh1,
    const float* dWhh0, const float* dWih1, const float* dWhh1,
    const float* ebih0, const float* ebhh0, const float* ebih1, const float* ebhh1,
    const float* dbih0, const float* dbhh0, const float* dbih1, const float* dbhh1)
{
    const float* Wsrc[6] = {eWhh0, eWih1, eWhh1, dWhh0, dWih1, dWhh1};
    const int fam[6] = {0, 1, 1, 2, 3, 3};
    float qw[6];
#pragma unroll
    for (int s = 0; s < 6; s++) qw[s] = __uint_as_float(g_fmax[fam[s]]) * (1.f / 16256.f);
    const float qwx = __uint_as_float(g_fmax[4]) * (1.f / 16256.f);

    const long stride = (long)gridDim.x * blockDim.x;
    const long i0 = (long)blockIdx.x * blockDim.x + threadIdx.x;

    // 6 weight matrices -> limb tiles
    const long totW = 6L * NTL * 8 * 96 * 128;
    for (long i = i0; i < totW; i += stride) {
        int bb = (int)(i % 128); long q = i / 128;
        int r  = (int)(q % 96);  q /= 96;
        int ch = (int)(q % 8);   q /= 8;
        int nt = (int)(q % NTL); int ty = (int)(q / NTL);
        int g = r >> 5, j = nt * 32 + (r & 31);
        int k = (bb < 64) ? bb : bb - 64;
        float W = Wsrc[ty][(size_t)(g * HD + j) * HD + ch * 64 + k];
        float ws = W / qw[ty];
        int w1 = clamp127(ws * (1.f / 128.f));
        int val = (bb < 64) ? w1 : clamp127(ws - w1 * 128.f);
        g_wq[ty][nt][ch][offb(r, bb)] = (signed char)val;
    }
    // enc0 Wih (K=32) -> [w1 32B | w2 32B | 0]
    const long totX = (long)NTL * 96 * 128;
    for (long i = i0; i < totX; i += stride) {
        int bb = (int)(i % 128); long q = i / 128;
        int r = (int)(q % 96);   int nt = (int)(q / 96);
        int g = r >> 5, j = nt * 32 + (r & 31);
        int val = 0;
        if (bb < 64) {
            int k = (bb < 32) ? bb : bb - 32;
            float W = eWih0[(size_t)(g * HD + j) * DIN + k];
            float ws = W / qwx;
            int w1 = clamp127(ws * (1.f / 128.f));
            val = (bb < 32) ? w1 : clamp127(ws - w1 * 128.f);
        }
        g_wxq[nt][offb(r, bb)] = (signed char)val;
    }
    // biases
    const float* bi[4] = {ebih0, ebih1, dbih0, dbih1};
    const float* bh[4] = {ebhh0, ebhh1, dbhh0, dbhh1};
    for (long i = i0; i < 4 * HD; i += stride) {
        int tt = (int)(i / HD), j = (int)(i % HD);
        g_br[tt][j]  = bi[tt][j] + bh[tt][j];
        g_bz[tt][j]  = bi[tt][HD + j] + bh[tt][HD + j];
        g_bin[tt][j] = bi[tt][2 * HD + j];
        g_bhn[tt][j] = bh[tt][2 * HD + j];
    }
    if (i0 == 0) {
        g_scale[0] = qw[0]; g_scale[1] = qw[2]; g_scale[2] = qw[3]; g_scale[3] = qw[5];
        g_sx[0] = 8.f * qwx;          // HI scale: 2^14 * 2^-11 * qwx
        g_sx[1] = qwx * (1.f / 16.f); // MID scale: 2^7 * 2^-11 * qwx
    }
}

__global__ void k_xq(const float* __restrict__ x)
{
    const long stride = (long)gridDim.x * blockDim.x;
    const long tot = (long)TSEQ * MT * 128 * 128;
    for (long i = (long)blockIdx.x * blockDim.x + threadIdx.x; i < tot; i += stride) {
        int bb = (int)(i % 128); long q = i / 128;
        int r = (int)(q % 128);  q /= 128;
        int mt = (int)(q % MT);  int t = (int)(q / MT);
        int val = 0;
        if (bb < 64) {
            int k = (bb < 32) ? bb : bb - 32;
            float v = x[((long)(mt * 128 + r) * TSEQ + t) * DIN + k];
            float t16 = v * 16.f;
            int x1 = clamp127(t16);
            val = (bb < 32) ? x1 : clamp127((t16 - x1) * 128.f);
        }
        g_xq[t][mt][offb(r, bb)] = (signed char)val;
    }
}

// ---------------- grid barrier ----------------
__device__ __forceinline__ void gbar()
{
    __syncthreads();
    if (threadIdx.x == 0) {
        __threadfence();
        unsigned gen = *(volatile unsigned*)&g_gen;
        unsigned t = atomicAdd(&g_cnt, 1u);
        if (t == NCTA - 1) {
            *(volatile unsigned*)&g_cnt = 0;
            __threadfence();
            *(volatile unsigned*)&g_gen = gen + 1;
        } else {
            while (*(volatile unsigned*)&g_gen == gen) __nanosleep(32);
        }
        __threadfence();
    }
    __syncthreads();
}

// ---------------- chunk compute: int8 limb MMA, 4m x 2n warps ----------------
// XK=0: K=64 chunk (2 k32 steps, limb2 at +64B). XK=1: x chunk (1 k32, limb2 at +32B).
template<int XK>
__device__ __forceinline__ void compute_chunk(
    uint32_t sbuf, int lane, int wm, int wn,
    int (&Rh)[2][2][4], int (&Rm)[2][2][4],
    int (&Zh)[2][2][4], int (&Zm)[2][2][4],
    int (&Nh)[2][2][4], int (&Nm)[2][2][4])
{
    const uint32_t sA = sbuf, sB = sbuf + A_TB;
    const int rl = lane & 15;
    const int c16 = (lane >> 4) * 16;
    const int NKQ = XK ? 1 : 2;
    const int L2O = XK ? 32 : 64;
#pragma unroll
    for (int kq = 0; kq < NKQ; kq++) {
        const int cb = kq * 32;
        uint32_t a1[2][4], a2[2][4];
#pragma unroll
        for (int mtl = 0; mtl < 2; mtl++) {
            const int row = wm * 32 + mtl * 16 + rl;
            LDSM4(a1[mtl], sA + offb(row, cb + c16));
            LDSM4(a2[mtl], sA + offb(row, L2O + cb + c16));
        }
#define GATEBLK(Hh, Hm, goff) do {                                        \
        uint32_t w1[4], w2[4];                                            \
        const int brow = (goff) + wn * 16 + rl;                           \
        LDSM4(w1, sB + offb(brow, cb + c16));                             \
        LDSM4(w2, sB + offb(brow, L2O + cb + c16));                       \
        _Pragma("unroll") for (int mtl = 0; mtl < 2; mtl++) {             \
            _Pragma("unroll") for (int n8 = 0; n8 < 2; n8++) {            \
                MMAI(Hh[mtl][n8], a1[mtl], w1[n8], w1[n8 + 2]);           \
                MMAI(Hm[mtl][n8], a1[mtl], w2[n8], w2[n8 + 2]);           \
                MMAI(Hm[mtl][n8], a2[mtl], w1[n8], w1[n8 + 2]);           \
            } } } while (0)
        GATEBLK(Rh, Rm, 0);
        GATEBLK(Zh, Zm, 32);
        GATEBLK(Nh, Nm, 64);
#undef GATEBLK
    }
}

struct Ck { const signed char* A; const signed char* B; };

// ---------------- persistent kernel ----------------
__global__ void __launch_bounds__(256, 1) gru_tc(
    const float* __restrict__ dWih0,
    const float* __restrict__ outW, const float* __restrict__ outb,
    const float* __restrict__ dstart, float* __restrict__ out)
{
    extern __shared__ char smem[];
    const int tid = threadIdx.x, wid = tid >> 5, lane = tid & 31;
    const int wm = wid & 3, wn = wid >> 2;
    const int mt = blockIdx.x >> 4, nt = blockIdx.x & 15;

    // ---- per-launch state init ----
    {
        const long gs = (long)NCTA * 256;
        for (long i = (long)blockIdx.x * 256 + tid; i < (long)BATCH * HD; i += gs) {
            g_h1[0][i] = 0.f; g_h2[0][i] = 0.f;
        }
        uint32_t* z1 = (uint32_t*)&g_h1q[0][0][0][0];
        uint32_t* z2 = (uint32_t*)&g_h2q[0][0][0][0];
        const long nz = (long)MT * 8 * A_TB / 4;
        for (long i = (long)blockIdx.x * 256 + tid; i < nz; i += gs) { z1[i] = 0; z2[i] = 0; }
        for (long i = (long)blockIdx.x * 256 + tid; i < BATCH; i += gs) g_y[i] = dstart[0];
    }
    gbar();

    int Rh[2][2][4], Rm[2][2][4], Zh[2][2][4], Zm[2][2][4];
    int NHh[2][2][4], NHm[2][2][4], NIh[2][2][4], NIm[2][2][4];
    float gxr[16], gxz[16], gxn[16];

    auto zeroRZ = [&]() {
#pragma unroll
        for (int a = 0; a < 2; a++)
#pragma unroll
            for (int b = 0; b < 2; b++)
#pragma unroll
                for (int c = 0; c < 4; c++) {
                    Rh[a][b][c] = 0; Rm[a][b][c] = 0;
                    Zh[a][b][c] = 0; Zm[a][b][c] = 0;
                }
    };
    auto zeroN = [&](int (&Ah)[2][2][4], int (&Am)[2][2][4]) {
#pragma unroll
        for (int a = 0; a < 2; a++)
#pragma unroll
            for (int b = 0; b < 2; b++)
#pragma unroll
                for (int c = 0; c < 4; c++) { Ah[a][b][c] = 0; Am[a][b][c] = 0; }
    };

    auto load_chunk = [&](int buf, const signed char* A, const signed char* B) {
        uint32_t d = smem_u32(smem) + buf * BUF_BYTES;
#pragma unroll
        for (int i = 0; i < 4; i++) CPA16(d + (tid + i * 256) * 16, A + (size_t)(tid + i * 256) * 16);
        uint32_t db = d + A_TB;
#pragma unroll
        for (int i = 0; i < 3; i++) CPA16(db + (tid + i * 256) * 16, B + (size_t)(tid + i * 256) * 16);
        CPCOMMIT();
    };

    auto run_seg = [&](const Ck* cks, int n, int (&Nh)[2][2][4], int (&Nm)[2][2][4]) {
        load_chunk(0, cks[0].A, cks[0].B);
        for (int i = 0; i < n; i++) {
            if (i + 1 < n) { load_chunk((i + 1) & 1, cks[i + 1].A, cks[i + 1].B); CPWAIT1(); }
            else CPWAIT0();
            __syncthreads();
            compute_chunk<0>(smem_u32(smem) + (i & 1) * BUF_BYTES, lane, wm, wn,
                             Rh, Rm, Zh, Zm, Nh, Nm);
            __syncthreads();
        }
    };

    // epilogue: mode 0 = enc-l0 (gx), 1 = layer1 (NI), 2 = dec-l0 (dec0W scalar)
    auto epilogue = [&](int bt, int mode, const float* hprev, float* hout,
                        signed char* hq, const float* dec0W) {
        const float scA = g_scale[bt], scB = scA * (1.f / 128.f);
        const int qr = lane >> 2, qc = lane & 3;
#pragma unroll
        for (int mtl = 0; mtl < 2; mtl++) {
#pragma unroll
            for (int fr = 0; fr < 2; fr++) {
                const int rloc = wm * 32 + mtl * 16 + qr + fr * 8;
                const int grow = mt * 128 + rloc;
                const float yy = (mode == 2) ? __ldcg(&g_y[grow]) : 0.f;
#pragma unroll
                for (int n8 = 0; n8 < 2; n8++) {
#pragma unroll
                    for (int e = 0; e < 2; e++) {
                        const int jl = wn * 16 + n8 * 8 + qc * 2 + e;
                        const int j = nt * 32 + jl;
                        const int ci = fr * 2 + e;
                        const int ox = (mtl * 2 + n8) * 4 + ci;
                        float rv = (float)Rh[mtl][n8][ci] * scA + (float)Rm[mtl][n8][ci] * scB;
                        float zv = (float)Zh[mtl][n8][ci] * scA + (float)Zm[mtl][n8][ci] * scB;
                        float nhv = (float)NHh[mtl][n8][ci] * scA + (float)NHm[mtl][n8][ci] * scB;
                        float niv;
                        if (mode == 0)      { rv += gxr[ox]; zv += gxz[ox]; niv = gxn[ox]; }
                        else if (mode == 1) { niv = (float)NIh[mtl][n8][ci] * scA + (float)NIm[mtl][n8][ci] * scB; }
                        else                { rv += yy * dec0W[j]; zv += yy * dec0W[HD + j];
                                              niv = yy * dec0W[2 * HD + j]; }
                        const float r = 1.f / (1.f + __expf(-(rv + g_br[bt][j])));
                        const float z = 1.f / (1.f + __expf(-(zv + g_bz[bt][j])));
                        const float n = tanhf(niv + g_bin[bt][j] + r * (nhv + g_bhn[bt][j]));
                        const float hp = hprev[(size_t)grow * HD + j];
                        const float hv = n + z * (hp - n);
                        hout[(size_t)grow * HD + j] = hv;
                        // quantize to limbs
                        const float th = hv * 128.f;
                        const int a1 = clamp127(th);
                        const int a2 = clamp127((th - a1) * 128.f);
                        const int kk = (nt & 1) * 32 + jl;
                        hq[offb(rloc, kk)] = (signed char)a1;
                        hq[offb(rloc, 64 + kk)] = (signed char)a2;
                    }
                }
            }
        }
    };

    Ck ckA[8], ckB[8];
    int p = 0;

    // ---------------- encoder: 512 steps ----------------
    for (int t = 0; t < TSEQ; t++) {
        // --- layer 0: x chunk first (own scale), then hidden GEMM ---
        zeroRZ(); zeroN(NIh, NIm);
        load_chunk(0, &g_xq[t][mt][0], &g_wxq[nt][0]);
        CPWAIT0(); __syncthreads();
        compute_chunk<1>(smem_u32(smem), lane, wm, wn, Rh, Rm, Zh, Zm, NIh, NIm);
        __syncthreads();
        {
            const float sxA = g_sx[0], sxB = g_sx[1];
#pragma unroll
            for (int a = 0; a < 2; a++)
#pragma unroll
                for (int b = 0; b < 2; b++)
#pragma unroll
                    for (int c = 0; c < 4; c++) {
                        const int ox = (a * 2 + b) * 4 + c;
                        gxr[ox] = (float)Rh[a][b][c] * sxA + (float)Rm[a][b][c] * sxB;
                        gxz[ox] = (float)Zh[a][b][c] * sxA + (float)Zm[a][b][c] * sxB;
                        gxn[ox] = (float)NIh[a][b][c] * sxA + (float)NIm[a][b][c] * sxB;
                    }
        }
        zeroRZ(); zeroN(NHh, NHm);
        for (int c = 0; c < 8; c++)
            ckA[c] = { &g_h1q[p][mt][c][0], &g_wq[0][nt][c][0] };
        run_seg(ckA, 8, NHh, NHm);
        epilogue(0, 0, g_h1[p], g_h1[1 - p], &g_h1q[1 - p][mt][nt >> 1][0], nullptr);
        // --- layer 1: hidden (old h2) before gbar, input (new h1) after ---
        for (int c = 0; c < 8; c++) {
            ckA[c] = { &g_h2q[p][mt][c][0], &g_wq[2][nt][c][0] };
            ckB[c] = { &g_h1q[1 - p][mt][c][0], &g_wq[1][nt][c][0] };
        }
        zeroRZ(); zeroN(NHh, NHm); zeroN(NIh, NIm);
        run_seg(ckA, 8, NHh, NHm);
        gbar();
        run_seg(ckB, 8, NIh, NIm);
        epilogue(1, 1, g_h2[p], g_h2[1 - p], &g_h2q[1 - p][mt][nt >> 1][0], nullptr);
        gbar();
        p ^= 1;
    }

    // ---------------- decoder: 96 steps ----------------
    for (int s = 0; s < PLEN; s++) {
        zeroRZ(); zeroN(NHh, NHm);
        for (int c = 0; c < 8; c++)
            ckA[c] = { &g_h1q[p][mt][c][0], &g_wq[3][nt][c][0] };
        run_seg(ckA, 8, NHh, NHm);
        epilogue(2, 2, g_h1[p], g_h1[1 - p], &g_h1q[1 - p][mt][nt >> 1][0], dWih0);
        for (int c = 0; c < 8; c++) {
            ckA[c] = { &g_h2q[p][mt][c][0], &g_wq[5][nt][c][0] };
            ckB[c] = { &g_h1q[1 - p][mt][c][0], &g_wq[4][nt][c][0] };
        }
        zeroRZ(); zeroN(NHh, NHm); zeroN(NIh, NIm);
        run_seg(ckA, 8, NHh, NHm);
        gbar();
        run_seg(ckB, 8, NIh, NIm);
        epilogue(3, 1, g_h2[p], g_h2[1 - p], &g_h2q[1 - p][mt][nt >> 1][0], nullptr);
        gbar();
        // projection: 8 rows per CTA, one warp each
        {
            const int row = blockIdx.x * 8 + wid;
            const float* hr = g_h2[1 - p] + (size_t)row * HD;
            float ss = 0.f;
#pragma unroll
            for (int q = 0; q < HD / 32; q++)
                ss += __ldcg(&hr[lane + 32 * q]) * outW[lane + 32 * q];
#pragma unroll
            for (int o = 16; o > 0; o >>= 1)
                ss += __shfl_xor_sync(0xffffffffu, ss, o);
            if (lane == 0) {
                const float v = ss + outb[0];
                g_y[row] = v;
                out[(size_t)row * PLEN + s] = v;
            }
        }
        gbar();
        p ^= 1;
    }
}

// ---------------------------------------------------------------------------
extern "C" void kernel_launch(void* const* d_in, const int* in_sizes, int n_in,
                              void* d_out, int out_size)
{
    const float* x      = (const float*)d_in[0];
    const float* eWih0  = (const float*)d_in[1];
    const float* eWhh0  = (const float*)d_in[2];
    const float* ebih0  = (const float*)d_in[3];
    const float* ebhh0  = (const float*)d_in[4];
    const float* eWih1  = (const float*)d_in[5];
    const float* eWhh1  = (const float*)d_in[6];
    const float* ebih1  = (const float*)d_in[7];
    const float* ebhh1  = (const float*)d_in[8];
    const float* dWih0  = (const float*)d_in[9];
    const float* dWhh0  = (const float*)d_in[10];
    const float* dbih0  = (const float*)d_in[11];
    const float* dbhh0  = (const float*)d_in[12];
    const float* dWih1  = (const float*)d_in[13];
    const float* dWhh1  = (const float*)d_in[14];
    const float* dbih1  = (const float*)d_in[15];
    const float* dbhh1  = (const float*)d_in[16];
    const float* outW   = (const float*)d_in[17];
    const float* outb   = (const float*)d_in[18];
    const float* dstart = (const float*)d_in[19];
    float* out = (float*)d_out;

    cudaFuncSetAttribute(gru_tc, cudaFuncAttributeMaxDynamicSharedMemorySize, SM_TOTAL);

    k_reset<<<1, 32>>>();
    k_maxw<<<512, 256>>>(eWhh0, eWih1, eWhh1, dWhh0, dWih1, dWhh1, eWih0);
    k_quant<<<1024, 256>>>(eWih0,
                           eWhh0, eWih1, eWhh1, dWhh0, dWih1, dWhh1,
                           ebih0, ebhh0, ebih1, ebhh1,
                           dbih0, dbhh0, dbih1, dbhh1);
    k_xq<<<2048, 256>>>(x);
    gru_tc<<<NCTA, 256, SM_TOTAL>>>(dWih0, outW, outb, dstart, out);
}

// round 9
// speedup vs baseline: 2.1189x; 2.1189x over previous
#include <cuda_runtime.h>
#include <cuda_bf16.h>
#include <cstdint>
#include <cstddef>

// ---------------- problem dims ----------------
#define HD    512
#define BATCH 1024
#define TSEQ  512
#define PLEN  96
#define DIN   32

// ---------------- tiling ----------------
#define NCTA 128
#define MT   8          // m-tiles (BATCH/128)
#define NTL  16         // n-tiles (HD/32)
#define BMR  128        // batch rows per CTA
#define BNR  96         // gate rows of W per CTA (3 gates x 32)
#define KC   64         // k per chunk

#define A_ELE (BMR*KC)  // 8192
#define B_ELE (BNR*KC)  // 6144
#define A_BYT (A_ELE*2) // 16384
#define B_BYT (B_ELE*2) // 12288
#define BUF_BYTES (2*A_BYT + 2*B_BYT)   // 57344
#define SM_TOTAL  (2*BUF_BYTES)         // 114688

// ---------------- device globals (static scratch) ----------------
__device__ float g_h1[2][BATCH*HD];
__device__ float g_h2[2][BATCH*HD];
__device__ __align__(16) __nv_bfloat16 g_h1bf[2][MT][8][2][A_ELE];
__device__ __align__(16) __nv_bfloat16 g_h2bf[2][MT][8][2][A_ELE];
__device__ __align__(16) __nv_bfloat16 g_xbf[TSEQ][MT][A_ELE];     // [xhi|xlo] k64
__device__ __align__(16) __nv_bfloat16 g_w[6][NTL][8][2][B_ELE];   // 0:e0hh 1:e1ih 2:e1hh 3:d0hh 4:d1ih 5:d1hh
__device__ __align__(16) __nv_bfloat16 g_wx[NTL][2][B_ELE];        // enc0 Wih: B1=[Whi|Whi], B2=[Wlo|0]
__device__ float g_br[4][HD], g_bz[4][HD], g_bin[4][HD], g_bhn[4][HD];
__device__ float g_y[BATCH];
__device__ unsigned g_cnt, g_gen;

// ---------------- tile addressing (ldmatrix-friendly swizzle) ----------------
__host__ __device__ __forceinline__ int offel(int r, int k) {
    return r * 64 + ((((k >> 3) ^ (r & 7)) << 3) | (k & 7));
}

// ---------------- PTX helpers ----------------
__device__ __forceinline__ uint32_t smem_u32(const void* p) {
    uint32_t a;
    asm("{ .reg .u64 t; cvta.to.shared.u64 t, %1; cvt.u32.u64 %0, t; }" : "=r"(a) : "l"(p));
    return a;
}
#define LDSM4(r, addr) asm volatile("ldmatrix.sync.aligned.m8n8.x4.shared.b16 {%0,%1,%2,%3},[%4];" \
    : "=r"((r)[0]), "=r"((r)[1]), "=r"((r)[2]), "=r"((r)[3]) : "r"(addr))
#define MMAB(d, a, b0, b1) asm volatile( \
    "mma.sync.aligned.m16n8k16.row.col.f32.bf16.bf16.f32 {%0,%1,%2,%3},{%4,%5,%6,%7},{%8,%9},{%0,%1,%2,%3};" \
    : "+f"((d)[0]), "+f"((d)[1]), "+f"((d)[2]), "+f"((d)[3]) \
    : "r"((a)[0]), "r"((a)[1]), "r"((a)[2]), "r"((a)[3]), "r"(b0), "r"(b1))
#define CPA16(sa, gp) asm volatile("cp.async.cg.shared.global [%0],[%1],16;" :: "r"(sa), "l"(gp))
#define CPCOMMIT()    asm volatile("cp.async.commit_group;" ::: "memory")
#define CPWAIT1()     asm volatile("cp.async.wait_group 1;" ::: "memory")
#define CPWAIT0()     asm volatile("cp.async.wait_group 0;" ::: "memory")

// ---------------- init kernels ----------------
__global__ void init_weights(
    const float* __restrict__ eWih0,
    const float* __restrict__ eWhh0, const float* __restrict__ eWih1, const float* __restrict__ eWhh1,
    const float* __restrict__ dWhh0, const float* __restrict__ dWih1, const float* __restrict__ dWhh1,
    const float* __restrict__ ebih0, const float* __restrict__ ebhh0,
    const float* __restrict__ ebih1, const float* __restrict__ ebhh1,
    const float* __restrict__ dbih0, const float* __restrict__ dbhh0,
    const float* __restrict__ dbih1, const float* __restrict__ dbhh1)
{
    const float* Wsrc[6] = {eWhh0, eWih1, eWhh1, dWhh0, dWih1, dWhh1};
    const long stride = (long)gridDim.x * blockDim.x;
    const long i0 = (long)blockIdx.x * blockDim.x + threadIdx.x;

    const long totW = 6L * NTL * 8 * BNR * KC;
    for (long i = i0; i < totW; i += stride) {
        int k = (int)(i % KC); long q = i / KC;
        int r = (int)(q % BNR); q /= BNR;
        int ch = (int)(q % 8); q /= 8;
        int nt = (int)(q % NTL); int ty = (int)(q / NTL);
        int g = r >> 5, jl = r & 31, j = nt * 32 + jl, kg = ch * KC + k;
        float v = Wsrc[ty][(size_t)(g * HD + j) * HD + kg];
        __nv_bfloat16 hi = __float2bfloat16(v);
        __nv_bfloat16 lo = __float2bfloat16(v - __bfloat162float(hi));
        int oe = offel(r, k);
        g_w[ty][nt][ch][0][oe] = hi;
        g_w[ty][nt][ch][1][oe] = lo;
    }
    // enc0 Wih (K=32): B1 = [Whi | Whi], B2 = [Wlo | 0]
    const long totX = (long)NTL * BNR * KC;
    for (long i = i0; i < totX; i += stride) {
        int k = (int)(i % KC); long q = i / KC;
        int r = (int)(q % BNR); int nt = (int)(q / BNR);
        int g = r >> 5, jl = r & 31, j = nt * 32 + jl, kk = k & 31;
        float v = eWih0[(size_t)(g * HD + j) * DIN + kk];
        __nv_bfloat16 hi = __float2bfloat16(v);
        __nv_bfloat16 lo = __float2bfloat16(v - __bfloat162float(hi));
        int oe = offel(r, k);
        g_wx[nt][0][oe] = hi;
        g_wx[nt][1][oe] = (k < 32) ? lo : __float2bfloat16(0.f);
    }
    const float* bi[4] = {ebih0, ebih1, dbih0, dbih1};
    const float* bh[4] = {ebhh0, ebhh1, dbhh0, dbhh1};
    for (long i = i0; i < 4 * HD; i += stride) {
        int tt = (int)(i / HD), j = (int)(i % HD);
        g_br[tt][j]  = bi[tt][j] + bh[tt][j];
        g_bz[tt][j]  = bi[tt][HD + j] + bh[tt][HD + j];
        g_bin[tt][j] = bi[tt][2 * HD + j];
        g_bhn[tt][j] = bh[tt][2 * HD + j];
    }
}

__global__ void init_x(const float* __restrict__ x)
{
    const long stride = (long)gridDim.x * blockDim.x;
    const long tot = (long)TSEQ * MT * BMR * KC;
    for (long i = (long)blockIdx.x * blockDim.x + threadIdx.x; i < tot; i += stride) {
        int k = (int)(i % KC); long q = i / KC;
        int r = (int)(q % BMR); q /= BMR;
        int mt = (int)(q % MT); int t = (int)(q / MT);
        int b = mt * BMR + r, c = k & 31;
        float v = x[((long)b * TSEQ + t) * DIN + c];
        __nv_bfloat16 hi = __float2bfloat16(v);
        __nv_bfloat16 val = (k < 32) ? hi : __float2bfloat16(v - __bfloat162float(hi));
        g_xbf[t][mt][offel(r, k)] = val;
    }
}

// ---------------- grid barrier ----------------
__device__ __forceinline__ void gbar()
{
    __syncthreads();
    if (threadIdx.x == 0) {
        __threadfence();
        unsigned gen = *(volatile unsigned*)&g_gen;
        unsigned t = atomicAdd(&g_cnt, 1u);
        if (t == NCTA - 1) {
            *(volatile unsigned*)&g_cnt = 0;
            __threadfence();
            *(volatile unsigned*)&g_gen = gen + 1;
        } else {
            while (*(volatile unsigned*)&g_gen == gen) __nanosleep(32);
        }
        __threadfence();
    }
    __syncthreads();
}

// ---------------- chunk compute: 2D warp tiling, product-pass ordering ----------------
// All B fragments (3 gates, hi+lo) loaded first; then 3 passes over the 12
// independent accumulators (hi*hi, lo*hi, hi*lo) so dependent MMAs to the same
// accumulator are >= 12 issues apart (covers MMA latency at any issue rate).
template<int MODE>
__device__ __forceinline__ void compute_chunk(
    uint32_t sbuf, int lane, int wm, int wn,
    float (&aR)[2][2][4], float (&aZ)[2][2][4],
    float (&aNH)[2][2][4], float (&aNI)[2][2][4])
{
    const uint32_t sA = sbuf, sAlo = sbuf + A_BYT;
    const uint32_t sB = sbuf + 2 * A_BYT, sBlo = sB + B_BYT;
    const int a_row = wm * 32 + (lane & 7) + ((lane >> 3) & 1) * 8;
    const int a_kh  = (lane >> 4) * 8;
    const int b_roff = (lane & 7) + ((lane >> 4) & 1) * 8;
    const int b_kh   = ((lane >> 3) & 1) * 8;

#pragma unroll
    for (int kq = 0; kq < 4; kq++) {
        const int kb = kq * 16;
        uint32_t ahi[2][4], alo[2][4];
        uint32_t bhi[3][4], blo[3][4];
#pragma unroll
        for (int mtl = 0; mtl < 2; mtl++) {
            const uint32_t ao = 2u * (uint32_t)offel(a_row + mtl * 16, kb + a_kh);
            LDSM4(ahi[mtl], sA + ao);
            if (MODE != 2) LDSM4(alo[mtl], sAlo + ao);
        }
#pragma unroll
        for (int g = 0; g < 3; g++) {
            const uint32_t bo = 2u * (uint32_t)offel(g * 32 + wn * 16 + b_roff, kb + b_kh);
            LDSM4(bhi[g], sB + bo);
            LDSM4(blo[g], sBlo + bo);
        }
#define DSTP(g, mtl, n8) ((g) == 0 ? aR[mtl][n8] : (g) == 1 ? aZ[mtl][n8] \
                          : (MODE == 0 ? aNH[mtl][n8] : aNI[mtl][n8]))
        // pass 1: hi * hi  (12 independent accumulators)
#pragma unroll
        for (int g = 0; g < 3; g++)
#pragma unroll
            for (int mtl = 0; mtl < 2; mtl++)
#pragma unroll
                for (int n8 = 0; n8 < 2; n8++)
                    MMAB(DSTP(g, mtl, n8), ahi[mtl], bhi[g][2 * n8], bhi[g][2 * n8 + 1]);
        // pass 2: lo * hi (skip for MODE 2)
        if (MODE != 2) {
#pragma unroll
            for (int g = 0; g < 3; g++)
#pragma unroll
                for (int mtl = 0; mtl < 2; mtl++)
#pragma unroll
                    for (int n8 = 0; n8 < 2; n8++)
                        MMAB(DSTP(g, mtl, n8), alo[mtl], bhi[g][2 * n8], bhi[g][2 * n8 + 1]);
        }
        // pass 3: hi * lo
#pragma unroll
        for (int g = 0; g < 3; g++)
#pragma unroll
            for (int mtl = 0; mtl < 2; mtl++)
#pragma unroll
                for (int n8 = 0; n8 < 2; n8++)
                    MMAB(DSTP(g, mtl, n8), ahi[mtl], blo[g][2 * n8], blo[g][2 * n8 + 1]);
#undef DSTP
    }
}

struct Ck { const char* A; const char* B; int mode; };

// ---------------- persistent kernel ----------------
__global__ void __launch_bounds__(256, 1) gru_tc(
    const float* __restrict__ dWih0,
    const float* __restrict__ outW, const float* __restrict__ outb,
    const float* __restrict__ dstart, float* __restrict__ out)
{
    extern __shared__ char smem[];
    const int tid = threadIdx.x, wid = tid >> 5, lane = tid & 31;
    const int wm = wid & 3, wn = wid >> 2;
    const int mt = blockIdx.x >> 4, nt = blockIdx.x & 15;

    // ---- per-launch state init ----
    {
        const long gs = (long)NCTA * 256;
        for (long i = (long)blockIdx.x * 256 + tid; i < (long)BATCH * HD; i += gs) {
            g_h1[0][i] = 0.f; g_h2[0][i] = 0.f;
        }
        uint32_t* z1 = (uint32_t*)&g_h1bf[0][0][0][0][0];
        uint32_t* z2 = (uint32_t*)&g_h2bf[0][0][0][0][0];
        const long nz = (long)MT * 8 * 2 * A_ELE / 2;
        for (long i = (long)blockIdx.x * 256 + tid; i < nz; i += gs) { z1[i] = 0; z2[i] = 0; }
        for (long i = (long)blockIdx.x * 256 + tid; i < BATCH; i += gs) g_y[i] = dstart[0];
    }
    gbar();

    float aR[2][2][4], aZ[2][2][4], aNH[2][2][4], aNI[2][2][4];

    auto zero_acc = [&]() {
#pragma unroll
        for (int a = 0; a < 2; a++)
#pragma unroll
            for (int b = 0; b < 2; b++)
#pragma unroll
                for (int c = 0; c < 4; c++) {
                    aR[a][b][c] = 0.f; aZ[a][b][c] = 0.f;
                    aNH[a][b][c] = 0.f; aNI[a][b][c] = 0.f;
                }
    };

    auto load_chunk = [&](int bufidx, const Ck& c) {
        uint32_t dst = smem_u32(smem) + bufidx * BUF_BYTES;
        const int nA = (c.mode == 2 ? A_BYT : 2 * A_BYT) >> 4;
        for (int i = tid; i < nA; i += 256) CPA16(dst + i * 16, c.A + i * 16);
        const uint32_t bdst = dst + 2 * A_BYT;
        for (int i = tid; i < (2 * B_BYT) >> 4; i += 256) CPA16(bdst + i * 16, c.B + i * 16);
        CPCOMMIT();
    };

    auto run_seg = [&](const Ck* cks, int n) {
        load_chunk(0, cks[0]);
        for (int i = 0; i < n; i++) {
            if (i + 1 < n) { load_chunk((i + 1) & 1, cks[i + 1]); CPWAIT1(); }
            else CPWAIT0();
            __syncthreads();
            const uint32_t sbuf = smem_u32(smem) + (i & 1) * BUF_BYTES;
            const int m = cks[i].mode;
            if (m == 0)      compute_chunk<0>(sbuf, lane, wm, wn, aR, aZ, aNH, aNI);
            else if (m == 1) compute_chunk<1>(sbuf, lane, wm, wn, aR, aZ, aNH, aNI);
            else             compute_chunk<2>(sbuf, lane, wm, wn, aR, aZ, aNH, aNI);
            __syncthreads();
        }
    };

    // epilogue: gates + state update. dec0W != null => decoder layer0 scalar input.
    auto epilogue = [&](int bt, const float* hprev, float* hout,
                        char* hbfbase, const float* dec0W) {
        const int qr = lane >> 2, qc = lane & 3;
        const int kbase = (nt & 1) * 32;
#pragma unroll
        for (int mtl = 0; mtl < 2; mtl++) {
#pragma unroll
            for (int fr = 0; fr < 2; fr++) {
                const int rloc = wm * 32 + mtl * 16 + qr + fr * 8;
                const int grow = mt * 128 + rloc;
                const float yy = dec0W ? __ldcg(&g_y[grow]) : 0.f;
#pragma unroll
                for (int n8 = 0; n8 < 2; n8++) {
#pragma unroll
                    for (int e = 0; e < 2; e++) {
                        const int jl = wn * 16 + n8 * 8 + qc * 2 + e;
                        const int j = nt * 32 + jl;
                        const int ci = fr * 2 + e;
                        float rv = aR[mtl][n8][ci], zv = aZ[mtl][n8][ci];
                        float nh = aNH[mtl][n8][ci], ni = aNI[mtl][n8][ci];
                        if (dec0W) {
                            rv += yy * dec0W[j];
                            zv += yy * dec0W[HD + j];
                            ni += yy * dec0W[2 * HD + j];
                        }
                        const float r = 1.f / (1.f + __expf(-(rv + g_br[bt][j])));
                        const float z = 1.f / (1.f + __expf(-(zv + g_bz[bt][j])));
                        const float n = tanhf(ni + g_bin[bt][j] + r * (nh + g_bhn[bt][j]));
                        const float hp = hprev[(size_t)grow * HD + j];
                        const float hv = n + z * (hp - n);
                        hout[(size_t)grow * HD + j] = hv;
                        __nv_bfloat16 hi = __float2bfloat16(hv);
                        __nv_bfloat16 lo = __float2bfloat16(hv - __bfloat162float(hi));
                        const int oe = offel(rloc, kbase + jl);
                        ((__nv_bfloat16*)hbfbase)[oe] = hi;
                        ((__nv_bfloat16*)(hbfbase + A_BYT))[oe] = lo;
                    }
                }
            }
        }
    };

    Ck ckA[9], ckB[8];
    int p = 0;

    // ---------------- encoder: 512 steps ----------------
    for (int t = 0; t < TSEQ; t++) {
        for (int c = 0; c < 8; c++)
            ckA[c] = { (const char*)&g_h1bf[p][mt][c][0][0],
                       (const char*)&g_w[0][nt][c][0][0], 0 };
        ckA[8] = { (const char*)&g_xbf[t][mt][0], (const char*)&g_wx[nt][0][0], 2 };
        zero_acc();
        run_seg(ckA, 9);
        epilogue(0, g_h1[p], g_h1[1 - p], (char*)&g_h1bf[1 - p][mt][nt >> 1][0][0], nullptr);
        // layer 1: hidden GEMM first (old h2), gbar, then input GEMM (new h1)
        for (int c = 0; c < 8; c++) {
            ckA[c] = { (const char*)&g_h2bf[p][mt][c][0][0],
                       (const char*)&g_w[2][nt][c][0][0], 0 };
            ckB[c] = { (const char*)&g_h1bf[1 - p][mt][c][0][0],
                       (const char*)&g_w[1][nt][c][0][0], 1 };
        }
        zero_acc();
        run_seg(ckA, 8);
        gbar();
        run_seg(ckB, 8);
        epilogue(1, g_h2[p], g_h2[1 - p], (char*)&g_h2bf[1 - p][mt][nt >> 1][0][0], nullptr);
        gbar();
        p ^= 1;
    }

    // ---------------- decoder: 96 steps ----------------
    for (int s = 0; s < PLEN; s++) {
        for (int c = 0; c < 8; c++)
            ckA[c] = { (const char*)&g_h1bf[p][mt][c][0][0],
                       (const char*)&g_w[3][nt][c][0][0], 0 };
        zero_acc();
        run_seg(ckA, 8);
        epilogue(2, g_h1[p], g_h1[1 - p], (char*)&g_h1bf[1 - p][mt][nt >> 1][0][0], dWih0);
        for (int c = 0; c < 8; c++) {
            ckA[c] = { (const char*)&g_h2bf[p][mt][c][0][0],
                       (const char*)&g_w[5][nt][c][0][0], 0 };
            ckB[c] = { (const char*)&g_h1bf[1 - p][mt][c][0][0],
                       (const char*)&g_w[4][nt][c][0][0], 1 };
        }
        zero_acc();
        run_seg(ckA, 8);
        gbar();
        run_seg(ckB, 8);
        epilogue(3, g_h2[p], g_h2[1 - p], (char*)&g_h2bf[1 - p][mt][nt >> 1][0][0], nullptr);
        gbar();
        {
            const int row = blockIdx.x * 8 + wid;
            const float* hr = g_h2[1 - p] + (size_t)row * HD;
            float ss = 0.f;
#pragma unroll
            for (int q = 0; q < HD / 32; q++)
                ss += __ldcg(&hr[lane + 32 * q]) * outW[lane + 32 * q];
#pragma unroll
            for (int o = 16; o > 0; o >>= 1)
                ss += __shfl_xor_sync(0xffffffffu, ss, o);
            if (lane == 0) {
                const float v = ss + outb[0];
                g_y[row] = v;
                out[(size_t)row * PLEN + s] = v;
            }
        }
        gbar();
        p ^= 1;
    }
}

// ---------------------------------------------------------------------------
extern "C" void kernel_launch(void* const* d_in, const int* in_sizes, int n_in,
                              void* d_out, int out_size)
{
    const float* x      = (const float*)d_in[0];
    const float* eWih0  = (const float*)d_in[1];
    const float* eWhh0  = (const float*)d_in[2];
    const float* ebih0  = (const float*)d_in[3];
    const float* ebhh0  = (const float*)d_in[4];
    const float* eWih1  = (const float*)d_in[5];
    const float* eWhh1  = (const float*)d_in[6];
    const float* ebih1  = (const float*)d_in[7];
    const float* ebhh1  = (const float*)d_in[8];
    const float* dWih0  = (const float*)d_in[9];
    const float* dWhh0  = (const float*)d_in[10];
    const float* dbih0  = (const float*)d_in[11];
    const float* dbhh0  = (const float*)d_in[12];
    const float* dWih1  = (const float*)d_in[13];
    const float* dWhh1  = (const float*)d_in[14];
    const float* dbih1  = (const float*)d_in[15];
    const float* dbhh1  = (const float*)d_in[16];
    const float* outW   = (const float*)d_in[17];
    const float* outb   = (const float*)d_in[18];
    const float* dstart = (const float*)d_in[19];
    float* out = (float*)d_out;

    cudaFuncSetAttribute(gru_tc, cudaFuncAttributeMaxDynamicSharedMemorySize, SM_TOTAL);

    init_weights<<<1024, 256>>>(eWih0,
                                eWhh0, eWih1, eWhh1, dWhh0, dWih1, dWhh1,
                                ebih0, ebhh0, ebih1, ebhh1,
                                dbih0, dbhh0, dbih1, dbhh1);
    init_x<<<2048, 256>>>(x);
    gru_tc<<<NCTA, 256, SM_TOTAL>>>(dWih0, outW, outb, dstart, out);
}

// round 10
// speedup vs baseline: 2.8133x; 1.3277x over previous
#include <cuda_runtime.h>
#include <cuda_fp16.h>
#include <cstdint>
#include <cstddef>

// ---------------- problem dims ----------------
#define HD    512
#define BATCH 1024
#define TSEQ  512
#define PLEN  96
#define DIN   32

// ---------------- tiling ----------------
#define NCTA 128
#define MT   8          // m-tiles (BATCH/128)
#define NTL  16         // n-tiles (HD/32)
#define BMR  128        // batch rows per CTA
#define BNR  96         // gate rows of W per CTA (3 gates x 32)
#define KC   64         // k per chunk

#define A_ELE (BMR*KC)  // 8192 halfs
#define B_ELE (BNR*KC)  // 6144 halfs
#define A_BYT (A_ELE*2) // 16384 (single A limb)
#define B_BYT (B_ELE*2) // 12288 per W limb
#define BUF_BYTES (A_BYT + 2*B_BYT)     // 40960
#define SM_TOTAL  (2*BUF_BYTES)         // 81920

#define WSCALE 1024.f
#define INVWS  (1.f/1024.f)

// ---------------- device globals (static scratch) ----------------
__device__ float g_h1[2][BATCH*HD];
__device__ float g_h2[2][BATCH*HD];
__device__ __align__(16) __half g_h1h[2][MT][8][A_ELE];
__device__ __align__(16) __half g_h2h[2][MT][8][A_ELE];
__device__ __align__(16) __half g_xh[TSEQ][MT][A_ELE];      // [xh(32)|0]
__device__ __align__(16) __half g_w[6][NTL][8][2][B_ELE];   // x1024; 0:e0hh 1:e1ih 2:e1hh 3:d0hh 4:d1ih 5:d1hh
__device__ __align__(16) __half g_wx[NTL][2][B_ELE];        // enc0 Wih x1024: [Wh(32)|0],[Wl(32)|0]
__device__ float g_br[4][HD], g_bz[4][HD], g_bin[4][HD], g_bhn[4][HD];
__device__ float g_y[BATCH];
__device__ unsigned g_cnt, g_gen;

// ---------------- tile addressing (ldmatrix-friendly swizzle) ----------------
__host__ __device__ __forceinline__ int offel(int r, int k) {
    return r * 64 + ((((k >> 3) ^ (r & 7)) << 3) | (k & 7));
}

// ---------------- PTX helpers ----------------
__device__ __forceinline__ uint32_t smem_u32(const void* p) {
    uint32_t a;
    asm("{ .reg .u64 t; cvta.to.shared.u64 t, %1; cvt.u32.u64 %0, t; }" : "=r"(a) : "l"(p));
    return a;
}
#define LDSM4(r, addr) asm volatile("ldmatrix.sync.aligned.m8n8.x4.shared.b16 {%0,%1,%2,%3},[%4];" \
    : "=r"((r)[0]), "=r"((r)[1]), "=r"((r)[2]), "=r"((r)[3]) : "r"(addr))
#define MMAH(d, a, b0, b1) asm volatile( \
    "mma.sync.aligned.m16n8k16.row.col.f32.f16.f16.f32 {%0,%1,%2,%3},{%4,%5,%6,%7},{%8,%9},{%0,%1,%2,%3};" \
    : "+f"((d)[0]), "+f"((d)[1]), "+f"((d)[2]), "+f"((d)[3]) \
    : "r"((a)[0]), "r"((a)[1]), "r"((a)[2]), "r"((a)[3]), "r"(b0), "r"(b1))
#define CPA16(sa, gp) asm volatile("cp.async.cg.shared.global [%0],[%1],16;" :: "r"(sa), "l"(gp))
#define CPCOMMIT()    asm volatile("cp.async.commit_group;" ::: "memory")
#define CPWAIT1()     asm volatile("cp.async.wait_group 1;" ::: "memory")
#define CPWAIT0()     asm volatile("cp.async.wait_group 0;" ::: "memory")

// ---------------- init kernels ----------------
__global__ void init_weights(
    const float* __restrict__ eWih0,
    const float* __restrict__ eWhh0, const float* __restrict__ eWih1, const float* __restrict__ eWhh1,
    const float* __restrict__ dWhh0, const float* __restrict__ dWih1, const float* __restrict__ dWhh1,
    const float* __restrict__ ebih0, const float* __restrict__ ebhh0,
    const float* __restrict__ ebih1, const float* __restrict__ ebhh1,
    const float* __restrict__ dbih0, const float* __restrict__ dbhh0,
    const float* __restrict__ dbih1, const float* __restrict__ dbhh1)
{
    const float* Wsrc[6] = {eWhh0, eWih1, eWhh1, dWhh0, dWih1, dWhh1};
    const long stride = (long)gridDim.x * blockDim.x;
    const long i0 = (long)blockIdx.x * blockDim.x + threadIdx.x;

    const long totW = 6L * NTL * 8 * BNR * KC;
    for (long i = i0; i < totW; i += stride) {
        int k = (int)(i % KC); long q = i / KC;
        int r = (int)(q % BNR); q /= BNR;
        int ch = (int)(q % 8); q /= 8;
        int nt = (int)(q % NTL); int ty = (int)(q / NTL);
        int g = r >> 5, jl = r & 31, j = nt * 32 + jl, kg = ch * KC + k;
        float v = Wsrc[ty][(size_t)(g * HD + j) * HD + kg] * WSCALE;
        __half hi = __float2half(v);
        __half lo = __float2half(v - __half2float(hi));
        int oe = offel(r, k);
        g_w[ty][nt][ch][0][oe] = hi;
        g_w[ty][nt][ch][1][oe] = lo;
    }
    // enc0 Wih (K=32): [Wh|0] and [Wl|0]
    const long totX = (long)NTL * BNR * KC;
    for (long i = i0; i < totX; i += stride) {
        int k = (int)(i % KC); long q = i / KC;
        int r = (int)(q % BNR); int nt = (int)(q / BNR);
        int g = r >> 5, jl = r & 31, j = nt * 32 + jl;
        __half hi = __float2half(0.f), lo = __float2half(0.f);
        if (k < 32) {
            float v = eWih0[(size_t)(g * HD + j) * DIN + k] * WSCALE;
            hi = __float2half(v);
            lo = __float2half(v - __half2float(hi));
        }
        int oe = offel(r, k);
        g_wx[nt][0][oe] = hi;
        g_wx[nt][1][oe] = lo;
    }
    const float* bi[4] = {ebih0, ebih1, dbih0, dbih1};
    const float* bh[4] = {ebhh0, ebhh1, dbhh0, dbhh1};
    for (long i = i0; i < 4 * HD; i += stride) {
        int tt = (int)(i / HD), j = (int)(i % HD);
        g_br[tt][j]  = bi[tt][j] + bh[tt][j];
        g_bz[tt][j]  = bi[tt][HD + j] + bh[tt][HD + j];
        g_bin[tt][j] = bi[tt][2 * HD + j];
        g_bhn[tt][j] = bh[tt][2 * HD + j];
    }
}

__global__ void init_x(const float* __restrict__ x)
{
    const long stride = (long)gridDim.x * blockDim.x;
    const long tot = (long)TSEQ * MT * BMR * KC;
    for (long i = (long)blockIdx.x * blockDim.x + threadIdx.x; i < tot; i += stride) {
        int k = (int)(i % KC); long q = i / KC;
        int r = (int)(q % BMR); q /= BMR;
        int mt = (int)(q % MT); int t = (int)(q / MT);
        __half val = __float2half(0.f);
        if (k < 32) {
            int b = mt * BMR + r;
            val = __float2half(x[((long)b * TSEQ + t) * DIN + k]);
        }
        g_xh[t][mt][offel(r, k)] = val;
    }
}

// ---------------- grid barrier ----------------
__device__ __forceinline__ void gbar()
{
    __syncthreads();
    if (threadIdx.x == 0) {
        __threadfence();
        unsigned gen = *(volatile unsigned*)&g_gen;
        unsigned t = atomicAdd(&g_cnt, 1u);
        if (t == NCTA - 1) {
            *(volatile unsigned*)&g_cnt = 0;
            __threadfence();
            *(volatile unsigned*)&g_gen = gen + 1;
        } else {
            while (*(volatile unsigned*)&g_gen == gen) __nanosleep(32);
        }
        __threadfence();
    }
    __syncthreads();
}

// ---------------- chunk compute: fp16 2-product, 4m x 2n warps ----------------
// MODE 0: hidden GEMM (n-gate -> aNH). MODE 1: input GEMM (n-gate -> aNI).
// Per (tile, k16): acc += Ah*Wh + Ah*Wl.
template<int MODE>
__device__ __forceinline__ void compute_chunk(
    uint32_t sbuf, int lane, int wm, int wn,
    float (&aR)[2][2][4], float (&aZ)[2][2][4],
    float (&aNH)[2][2][4], float (&aNI)[2][2][4])
{
    const uint32_t sA = sbuf;
    const uint32_t sB = sbuf + A_BYT, sBlo = sB + B_BYT;
    const int a_row = wm * 32 + (lane & 7) + ((lane >> 3) & 1) * 8;
    const int a_kh  = (lane >> 4) * 8;
    const int b_roff = (lane & 7) + ((lane >> 4) & 1) * 8;
    const int b_kh   = ((lane >> 3) & 1) * 8;

#pragma unroll
    for (int kq = 0; kq < 4; kq++) {
        const int kb = kq * 16;
        uint32_t ahi[2][4];
#pragma unroll
        for (int mtl = 0; mtl < 2; mtl++)
            LDSM4(ahi[mtl], sA + 2u * (uint32_t)offel(a_row + mtl * 16, kb + a_kh));
#pragma unroll
        for (int g = 0; g < 3; g++) {
            const uint32_t bo = 2u * (uint32_t)offel(g * 32 + wn * 16 + b_roff, kb + b_kh);
            uint32_t bhi[4], blo[4];
            LDSM4(bhi, sB + bo);
            LDSM4(blo, sBlo + bo);
#pragma unroll
            for (int mtl = 0; mtl < 2; mtl++) {
#pragma unroll
                for (int n8 = 0; n8 < 2; n8++) {
                    float* dst = (g == 0) ? aR[mtl][n8]
                               : (g == 1) ? aZ[mtl][n8]
                               : (MODE == 0 ? aNH[mtl][n8] : aNI[mtl][n8]);
                    MMAH(dst, ahi[mtl], bhi[2 * n8], bhi[2 * n8 + 1]);
                    MMAH(dst, ahi[mtl], blo[2 * n8], blo[2 * n8 + 1]);
                }
            }
        }
    }
}

struct Ck { const __half* A; const __half* B; int mode; };

// ---------------- persistent kernel ----------------
__global__ void __launch_bounds__(256, 1) gru_tc(
    const float* __restrict__ dWih0,
    const float* __restrict__ outW, const float* __restrict__ outb,
    const float* __restrict__ dstart, float* __restrict__ out)
{
    extern __shared__ char smem[];
    const int tid = threadIdx.x, wid = tid >> 5, lane = tid & 31;
    const int wm = wid & 3, wn = wid >> 2;
    const int mt = blockIdx.x >> 4, nt = blockIdx.x & 15;

    // ---- per-launch state init ----
    {
        const long gs = (long)NCTA * 256;
        for (long i = (long)blockIdx.x * 256 + tid; i < (long)BATCH * HD; i += gs) {
            g_h1[0][i] = 0.f; g_h2[0][i] = 0.f;
        }
        uint32_t* z1 = (uint32_t*)&g_h1h[0][0][0][0];
        uint32_t* z2 = (uint32_t*)&g_h2h[0][0][0][0];
        const long nz = (long)MT * 8 * A_ELE / 2;
        for (long i = (long)blockIdx.x * 256 + tid; i < nz; i += gs) { z1[i] = 0; z2[i] = 0; }
        for (long i = (long)blockIdx.x * 256 + tid; i < BATCH; i += gs) g_y[i] = dstart[0];
    }
    gbar();

    float aR[2][2][4], aZ[2][2][4], aNH[2][2][4], aNI[2][2][4];

    auto zero_acc = [&]() {
#pragma unroll
        for (int a = 0; a < 2; a++)
#pragma unroll
            for (int b = 0; b < 2; b++)
#pragma unroll
                for (int c = 0; c < 4; c++) {
                    aR[a][b][c] = 0.f; aZ[a][b][c] = 0.f;
                    aNH[a][b][c] = 0.f; aNI[a][b][c] = 0.f;
                }
    };

    auto load_chunk = [&](int bufidx, const Ck& c) {
        uint32_t dst = smem_u32(smem) + bufidx * BUF_BYTES;
        const char* A = (const char*)c.A;
        const char* B = (const char*)c.B;
#pragma unroll
        for (int i = 0; i < 4; i++)
            CPA16(dst + (tid + i * 256) * 16, A + (size_t)(tid + i * 256) * 16);
        const uint32_t bdst = dst + A_BYT;
#pragma unroll
        for (int i = 0; i < 6; i++)
            CPA16(bdst + (tid + i * 256) * 16, B + (size_t)(tid + i * 256) * 16);
        CPCOMMIT();
    };

    auto run_seg = [&](const Ck* cks, int n) {
        load_chunk(0, cks[0]);
        for (int i = 0; i < n; i++) {
            if (i + 1 < n) { load_chunk((i + 1) & 1, cks[i + 1]); CPWAIT1(); }
            else CPWAIT0();
            __syncthreads();
            const uint32_t sbuf = smem_u32(smem) + (i & 1) * BUF_BYTES;
            if (cks[i].mode == 0) compute_chunk<0>(sbuf, lane, wm, wn, aR, aZ, aNH, aNI);
            else                  compute_chunk<1>(sbuf, lane, wm, wn, aR, aZ, aNH, aNI);
            __syncthreads();
        }
    };

    // epilogue: gates + state update. dec0W != null => decoder layer0 scalar input.
    auto epilogue = [&](int bt, const float* hprev, float* hout,
                        __half* hq, const float* dec0W) {
        const int qr = lane >> 2, qc = lane & 3;
        const int kbase = (nt & 1) * 32;
#pragma unroll
        for (int mtl = 0; mtl < 2; mtl++) {
#pragma unroll
            for (int fr = 0; fr < 2; fr++) {
                const int rloc = wm * 32 + mtl * 16 + qr + fr * 8;
                const int grow = mt * 128 + rloc;
                const float yy = dec0W ? __ldcg(&g_y[grow]) : 0.f;
#pragma unroll
                for (int n8 = 0; n8 < 2; n8++) {
#pragma unroll
                    for (int e = 0; e < 2; e++) {
                        const int jl = wn * 16 + n8 * 8 + qc * 2 + e;
                        const int j = nt * 32 + jl;
                        const int ci = fr * 2 + e;
                        float rv = aR[mtl][n8][ci] * INVWS;
                        float zv = aZ[mtl][n8][ci] * INVWS;
                        float nh = aNH[mtl][n8][ci] * INVWS;
                        float ni;
                        if (dec0W) {
                            rv += yy * dec0W[j];
                            zv += yy * dec0W[HD + j];
                            ni  = yy * dec0W[2 * HD + j];
                        } else {
                            ni = aNI[mtl][n8][ci] * INVWS;
                        }
                        const float r = 1.f / (1.f + __expf(-(rv + g_br[bt][j])));
                        const float z = 1.f / (1.f + __expf(-(zv + g_bz[bt][j])));
                        const float n = tanhf(ni + g_bin[bt][j] + r * (nh + g_bhn[bt][j]));
                        const float hp = hprev[(size_t)grow * HD + j];
                        const float hv = n + z * (hp - n);
                        hout[(size_t)grow * HD + j] = hv;
                        hq[offel(rloc, kbase + jl)] = __float2half(hv);
                    }
                }
            }
        }
    };

    Ck ckA[9], ckB[8];
    int p = 0;

    // ---------------- encoder: 512 steps ----------------
    for (int t = 0; t < TSEQ; t++) {
        // layer 0: 8 hidden chunks (mode 0) + x chunk (mode 1)
        for (int c = 0; c < 8; c++)
            ckA[c] = { &g_h1h[p][mt][c][0], &g_w[0][nt][c][0][0], 0 };
        ckA[8] = { &g_xh[t][mt][0], &g_wx[nt][0][0], 1 };
        zero_acc();
        run_seg(ckA, 9);
        epilogue(0, g_h1[p], g_h1[1 - p], &g_h1h[1 - p][mt][nt >> 1][0], nullptr);
        // layer 1: hidden GEMM first (old h2), gbar, then input GEMM (new h1)
        for (int c = 0; c < 8; c++) {
            ckA[c] = { &g_h2h[p][mt][c][0], &g_w[2][nt][c][0][0], 0 };
            ckB[c] = { &g_h1h[1 - p][mt][c][0], &g_w[1][nt][c][0][0], 1 };
        }
        zero_acc();
        run_seg(ckA, 8);
        gbar();
        run_seg(ckB, 8);
        epilogue(1, g_h2[p], g_h2[1 - p], &g_h2h[1 - p][mt][nt >> 1][0], nullptr);
        gbar();
        p ^= 1;
    }

    // ---------------- decoder: 96 steps ----------------
    for (int s = 0; s < PLEN; s++) {
        for (int c = 0; c < 8; c++)
            ckA[c] = { &g_h1h[p][mt][c][0], &g_w[3][nt][c][0][0], 0 };
        zero_acc();
        run_seg(ckA, 8);
        epilogue(2, g_h1[p], g_h1[1 - p], &g_h1h[1 - p][mt][nt >> 1][0], dWih0);
        for (int c = 0; c < 8; c++) {
            ckA[c] = { &g_h2h[p][mt][c][0], &g_w[5][nt][c][0][0], 0 };
            ckB[c] = { &g_h1h[1 - p][mt][c][0], &g_w[4][nt][c][0][0], 1 };
        }
        zero_acc();
        run_seg(ckA, 8);
        gbar();
        run_seg(ckB, 8);
        epilogue(3, g_h2[p], g_h2[1 - p], &g_h2h[1 - p][mt][nt >> 1][0], nullptr);
        gbar();
        // projection: 8 rows per CTA, one warp each
        {
            const int row = blockIdx.x * 8 + wid;
            const float* hr = g_h2[1 - p] + (size_t)row * HD;
            float ss = 0.f;
#pragma unroll
            for (int q = 0; q < HD / 32; q++)
                ss += __ldcg(&hr[lane + 32 * q]) * outW[lane + 32 * q];
#pragma unroll
            for (int o = 16; o > 0; o >>= 1)
                ss += __shfl_xor_sync(0xffffffffu, ss, o);
            if (lane == 0) {
                const float v = ss + outb[0];
                g_y[row] = v;
                out[(size_t)row * PLEN + s] = v;
            }
        }
        gbar();
        p ^= 1;
    }
}

// ---------------------------------------------------------------------------
extern "C" void kernel_launch(void* const* d_in, const int* in_sizes, int n_in,
                              void* d_out, int out_size)
{
    const float* x      = (const float*)d_in[0];
    const float* eWih0  = (const float*)d_in[1];
    const float* eWhh0  = (const float*)d_in[2];
    const float* ebih0  = (const float*)d_in[3];
    const float* ebhh0  = (const float*)d_in[4];
    const float* eWih1  = (const float*)d_in[5];
    const float* eWhh1  = (const float*)d_in[6];
    const float* ebih1  = (const float*)d_in[7];
    const float* ebhh1  = (const float*)d_in[8];
    const float* dWih0  = (const float*)d_in[9];
    const float* dWhh0  = (const float*)d_in[10];
    const float* dbih0  = (const float*)d_in[11];
    const float* dbhh0  = (const float*)d_in[12];
    const float* dWih1  = (const float*)d_in[13];
    const float* dWhh1  = (const float*)d_in[14];
    const float* dbih1  = (const float*)d_in[15];
    const float* dbhh1  = (const float*)d_in[16];
    const float* outW   = (const float*)d_in[17];
    const float* outb   = (const float*)d_in[18];
    const float* dstart = (const float*)d_in[19];
    float* out = (float*)d_out;

    cudaFuncSetAttribute(gru_tc, cudaFuncAttributeMaxDynamicSharedMemorySize, SM_TOTAL);

    init_weights<<<1024, 256>>>(eWih0,
                                eWhh0, eWih1, eWhh1, dWhh0, dWih1, dWhh1,
                                ebih0, ebhh0, ebih1, ebhh1,
                                dbih0, dbhh0, dbih1, dbhh1);
    init_x<<<2048, 256>>>(x);
    gru_tc<<<NCTA, 256, SM_TOTAL>>>(dWih0, outW, outb, dstart, out);
}

// round 11
// speedup vs baseline: 3.3017x; 1.1736x over previous
#include <cuda_runtime.h>
#include <cuda_fp16.h>
#include <cstdint>
#include <cstddef>

// ---------------- problem dims ----------------
#define HD    512
#define BATCH 1024
#define TSEQ  512
#define PLEN  96
#define DIN   32

// ---------------- tiling ----------------
#define NCTA 128
#define MT   8          // m-tiles (BATCH/128)
#define NTL  16         // n-tiles (HD/32)
#define BMR  128        // batch rows per CTA
#define BNR  96         // gate rows of W per CTA (3 gates x 32)
#define KC   64         // k per chunk

#define A_ELE (BMR*KC)  // 8192 halfs
#define B_ELE (BNR*KC)  // 6144 halfs
#define A_BYT (A_ELE*2) // 16384 (single A limb)
#define B_BYT (B_ELE*2) // 12288 per W limb
#define BUF_BYTES (A_BYT + 2*B_BYT)     // 40960
#define SM_TOTAL  (2*BUF_BYTES)         // 81920

#define WSCALE 1024.f
#define INVWS  (1.f/1024.f)

// ---------------- device globals (static scratch) ----------------
__device__ float g_h1[2][BATCH*HD];
__device__ float g_h2[2][BATCH*HD];
__device__ __align__(16) __half g_h1h[2][MT][8][A_ELE];
__device__ __align__(16) __half g_h2h[2][MT][8][A_ELE];
__device__ __align__(16) __half g_xh[TSEQ][MT][A_ELE];      // [xh(32)|0]
__device__ __align__(16) __half g_w[6][NTL][8][2][B_ELE];   // x1024; 0:e0hh 1:e1ih 2:e1hh 3:d0hh 4:d1ih 5:d1hh
__device__ __align__(16) __half g_wx[NTL][2][B_ELE];        // enc0 Wih x1024: [Wh(32)|0],[Wl(32)|0]
__device__ float g_br[4][HD], g_bz[4][HD], g_bin[4][HD], g_bhn[4][HD];
__device__ float g_y[BATCH];
__device__ unsigned g_cnt, g_gen;

// ---------------- tile addressing (ldmatrix-friendly swizzle) ----------------
__host__ __device__ __forceinline__ int offel(int r, int k) {
    return r * 64 + ((((k >> 3) ^ (r & 7)) << 3) | (k & 7));
}

// ---------------- PTX helpers ----------------
__device__ __forceinline__ uint32_t smem_u32(const void* p) {
    uint32_t a;
    asm("{ .reg .u64 t; cvta.to.shared.u64 t, %1; cvt.u32.u64 %0, t; }" : "=r"(a) : "l"(p));
    return a;
}
#define LDSM4(r, addr) asm volatile("ldmatrix.sync.aligned.m8n8.x4.shared.b16 {%0,%1,%2,%3},[%4];" \
    : "=r"((r)[0]), "=r"((r)[1]), "=r"((r)[2]), "=r"((r)[3]) : "r"(addr))
#define MMAH(d, a, b0, b1) asm volatile( \
    "mma.sync.aligned.m16n8k16.row.col.f32.f16.f16.f32 {%0,%1,%2,%3},{%4,%5,%6,%7},{%8,%9},{%0,%1,%2,%3};" \
    : "+f"((d)[0]), "+f"((d)[1]), "+f"((d)[2]), "+f"((d)[3]) \
    : "r"((a)[0]), "r"((a)[1]), "r"((a)[2]), "r"((a)[3]), "r"(b0), "r"(b1))
#define CPA16(sa, gp) asm volatile("cp.async.cg.shared.global [%0],[%1],16;" :: "r"(sa), "l"(gp))
#define CPCOMMIT()    asm volatile("cp.async.commit_group;" ::: "memory")
#define CPWAIT1()     asm volatile("cp.async.wait_group 1;" ::: "memory")
#define CPWAIT0()     asm volatile("cp.async.wait_group 0;" ::: "memory")

// ---------------- init kernels ----------------
__global__ void init_weights(
    const float* __restrict__ eWih0,
    const float* __restrict__ eWhh0, const float* __restrict__ eWih1, const float* __restrict__ eWhh1,
    const float* __restrict__ dWhh0, const float* __restrict__ dWih1, const float* __restrict__ dWhh1,
    const float* __restrict__ ebih0, const float* __restrict__ ebhh0,
    const float* __restrict__ ebih1, const float* __restrict__ ebhh1,
    const float* __restrict__ dbih0, const float* __restrict__ dbhh0,
    const float* __restrict__ dbih1, const float* __restrict__ dbhh1)
{
    const float* Wsrc[6] = {eWhh0, eWih1, eWhh1, dWhh0, dWih1, dWhh1};
    const long stride = (long)gridDim.x * blockDim.x;
    const long i0 = (long)blockIdx.x * blockDim.x + threadIdx.x;

    const long totW = 6L * NTL * 8 * BNR * KC;
    for (long i = i0; i < totW; i += stride) {
        int k = (int)(i % KC); long q = i / KC;
        int r = (int)(q % BNR); q /= BNR;
        int ch = (int)(q % 8); q /= 8;
        int nt = (int)(q % NTL); int ty = (int)(q / NTL);
        int g = r >> 5, jl = r & 31, j = nt * 32 + jl, kg = ch * KC + k;
        float v = Wsrc[ty][(size_t)(g * HD + j) * HD + kg] * WSCALE;
        __half hi = __float2half(v);
        __half lo = __float2half(v - __half2float(hi));
        int oe = offel(r, k);
        g_w[ty][nt][ch][0][oe] = hi;
        g_w[ty][nt][ch][1][oe] = lo;
    }
    // enc0 Wih (K=32): [Wh|0] and [Wl|0]
    const long totX = (long)NTL * BNR * KC;
    for (long i = i0; i < totX; i += stride) {
        int k = (int)(i % KC); long q = i / KC;
        int r = (int)(q % BNR); int nt = (int)(q / BNR);
        int g = r >> 5, jl = r & 31, j = nt * 32 + jl;
        __half hi = __float2half(0.f), lo = __float2half(0.f);
        if (k < 32) {
            float v = eWih0[(size_t)(g * HD + j) * DIN + k] * WSCALE;
            hi = __float2half(v);
            lo = __float2half(v - __half2float(hi));
        }
        int oe = offel(r, k);
        g_wx[nt][0][oe] = hi;
        g_wx[nt][1][oe] = lo;
    }
    const float* bi[4] = {ebih0, ebih1, dbih0, dbih1};
    const float* bh[4] = {ebhh0, ebhh1, dbhh0, dbhh1};
    for (long i = i0; i < 4 * HD; i += stride) {
        int tt = (int)(i / HD), j = (int)(i % HD);
        g_br[tt][j]  = bi[tt][j] + bh[tt][j];
        g_bz[tt][j]  = bi[tt][HD + j] + bh[tt][HD + j];
        g_bin[tt][j] = bi[tt][2 * HD + j];
        g_bhn[tt][j] = bh[tt][2 * HD + j];
    }
}

__global__ void init_x(const float* __restrict__ x)
{
    const long stride = (long)gridDim.x * blockDim.x;
    const long tot = (long)TSEQ * MT * BMR * KC;
    for (long i = (long)blockIdx.x * blockDim.x + threadIdx.x; i < tot; i += stride) {
        int k = (int)(i % KC); long q = i / KC;
        int r = (int)(q % BMR); q /= BMR;
        int mt = (int)(q % MT); int t = (int)(q / MT);
        __half val = __float2half(0.f);
        if (k < 32) {
            int b = mt * BMR + r;
            val = __float2half(x[((long)b * TSEQ + t) * DIN + k]);
        }
        g_xh[t][mt][offel(r, k)] = val;
    }
}

// ---------------- grid barrier ----------------
__device__ __forceinline__ void gbar()
{
    __syncthreads();
    if (threadIdx.x == 0) {
        __threadfence();
        unsigned gen = *(volatile unsigned*)&g_gen;
        unsigned t = atomicAdd(&g_cnt, 1u);
        if (t == NCTA - 1) {
            *(volatile unsigned*)&g_cnt = 0;
            __threadfence();
            *(volatile unsigned*)&g_gen = gen + 1;
        } else {
            while (*(volatile unsigned*)&g_gen == gen) __nanosleep(32);
        }
        __threadfence();
    }
    __syncthreads();
}

// ---------------- chunk compute: fp16 asymmetric products, 4m x 2n warps ----------------
// r,z gates: single product A*W_hi (fp16 W-quant error, damped by sigmoid).
// n gate:    two products A*W_hi + A*W_lo (full precision path into tanh).
// MODE 0: hidden GEMM (n -> aNH). MODE 1: input GEMM (n -> aNI).
template<int MODE>
__device__ __forceinline__ void compute_chunk(
    uint32_t sbuf, int lane, int wm, int wn,
    float (&aR)[2][2][4], float (&aZ)[2][2][4],
    float (&aNH)[2][2][4], float (&aNI)[2][2][4])
{
    const uint32_t sA = sbuf;
    const uint32_t sB = sbuf + A_BYT, sBlo = sB + B_BYT;
    const int a_row = wm * 32 + (lane & 7) + ((lane >> 3) & 1) * 8;
    const int a_kh  = (lane >> 4) * 8;
    const int b_roff = (lane & 7) + ((lane >> 4) & 1) * 8;
    const int b_kh   = ((lane >> 3) & 1) * 8;

#pragma unroll
    for (int kq = 0; kq < 4; kq++) {
        const int kb = kq * 16;
        uint32_t ahi[2][4];
#pragma unroll
        for (int mtl = 0; mtl < 2; mtl++)
            LDSM4(ahi[mtl], sA + 2u * (uint32_t)offel(a_row + mtl * 16, kb + a_kh));
#pragma unroll
        for (int g = 0; g < 3; g++) {
            const uint32_t bo = 2u * (uint32_t)offel(g * 32 + wn * 16 + b_roff, kb + b_kh);
            uint32_t bhi[4];
            LDSM4(bhi, sB + bo);
            if (g < 2) {
#pragma unroll
                for (int mtl = 0; mtl < 2; mtl++)
#pragma unroll
                    for (int n8 = 0; n8 < 2; n8++) {
                        float* dst = (g == 0) ? aR[mtl][n8] : aZ[mtl][n8];
                        MMAH(dst, ahi[mtl], bhi[2 * n8], bhi[2 * n8 + 1]);
                    }
            } else {
                uint32_t blo[4];
                LDSM4(blo, sBlo + bo);
#pragma unroll
                for (int mtl = 0; mtl < 2; mtl++)
#pragma unroll
                    for (int n8 = 0; n8 < 2; n8++) {
                        float* dst = (MODE == 0) ? aNH[mtl][n8] : aNI[mtl][n8];
                        MMAH(dst, ahi[mtl], bhi[2 * n8], bhi[2 * n8 + 1]);
                        MMAH(dst, ahi[mtl], blo[2 * n8], blo[2 * n8 + 1]);
                    }
            }
        }
    }
}

struct Ck { const __half* A; const __half* B; int mode; };

// ---------------- persistent kernel ----------------
__global__ void __launch_bounds__(256, 1) gru_tc(
    const float* __restrict__ dWih0,
    const float* __restrict__ outW, const float* __restrict__ outb,
    const float* __restrict__ dstart, float* __restrict__ out)
{
    extern __shared__ char smem[];
    const int tid = threadIdx.x, wid = tid >> 5, lane = tid & 31;
    const int wm = wid & 3, wn = wid >> 2;
    const int mt = blockIdx.x >> 4, nt = blockIdx.x & 15;

    // ---- per-launch state init ----
    {
        const long gs = (long)NCTA * 256;
        for (long i = (long)blockIdx.x * 256 + tid; i < (long)BATCH * HD; i += gs) {
            g_h1[0][i] = 0.f; g_h2[0][i] = 0.f;
        }
        uint32_t* z1 = (uint32_t*)&g_h1h[0][0][0][0];
        uint32_t* z2 = (uint32_t*)&g_h2h[0][0][0][0];
        const long nz = (long)MT * 8 * A_ELE / 2;
        for (long i = (long)blockIdx.x * 256 + tid; i < nz; i += gs) { z1[i] = 0; z2[i] = 0; }
        for (long i = (long)blockIdx.x * 256 + tid; i < BATCH; i += gs) g_y[i] = dstart[0];
    }
    gbar();

    float aR[2][2][4], aZ[2][2][4], aNH[2][2][4], aNI[2][2][4];

    auto zero_acc = [&]() {
#pragma unroll
        for (int a = 0; a < 2; a++)
#pragma unroll
            for (int b = 0; b < 2; b++)
#pragma unroll
                for (int c = 0; c < 4; c++) {
                    aR[a][b][c] = 0.f; aZ[a][b][c] = 0.f;
                    aNH[a][b][c] = 0.f; aNI[a][b][c] = 0.f;
                }
    };

    auto load_chunk = [&](int bufidx, const Ck& c) {
        uint32_t dst = smem_u32(smem) + bufidx * BUF_BYTES;
        const char* A = (const char*)c.A;
        const char* B = (const char*)c.B;
#pragma unroll
        for (int i = 0; i < 4; i++)
            CPA16(dst + (tid + i * 256) * 16, A + (size_t)(tid + i * 256) * 16);
        const uint32_t bdst = dst + A_BYT;
#pragma unroll
        for (int i = 0; i < 6; i++)
            CPA16(bdst + (tid + i * 256) * 16, B + (size_t)(tid + i * 256) * 16);
        CPCOMMIT();
    };

    auto run_seg = [&](const Ck* cks, int n) {
        load_chunk(0, cks[0]);
        for (int i = 0; i < n; i++) {
            if (i + 1 < n) { load_chunk((i + 1) & 1, cks[i + 1]); CPWAIT1(); }
            else CPWAIT0();
            __syncthreads();
            const uint32_t sbuf = smem_u32(smem) + (i & 1) * BUF_BYTES;
            if (cks[i].mode == 0) compute_chunk<0>(sbuf, lane, wm, wn, aR, aZ, aNH, aNI);
            else                  compute_chunk<1>(sbuf, lane, wm, wn, aR, aZ, aNH, aNI);
            __syncthreads();
        }
    };

    // epilogue: gates + state update. dec0W != null => decoder layer0 scalar input.
    auto epilogue = [&](int bt, const float* hprev, float* hout,
                        __half* hq, const float* dec0W) {
        const int qr = lane >> 2, qc = lane & 3;
        const int kbase = (nt & 1) * 32;
#pragma unroll
        for (int mtl = 0; mtl < 2; mtl++) {
#pragma unroll
            for (int fr = 0; fr < 2; fr++) {
                const int rloc = wm * 32 + mtl * 16 + qr + fr * 8;
                const int grow = mt * 128 + rloc;
                const float yy = dec0W ? __ldcg(&g_y[grow]) : 0.f;
#pragma unroll
                for (int n8 = 0; n8 < 2; n8++) {
#pragma unroll
                    for (int e = 0; e < 2; e++) {
                        const int jl = wn * 16 + n8 * 8 + qc * 2 + e;
                        const int j = nt * 32 + jl;
                        const int ci = fr * 2 + e;
                        float rv = aR[mtl][n8][ci] * INVWS;
                        float zv = aZ[mtl][n8][ci] * INVWS;
                        float nh = aNH[mtl][n8][ci] * INVWS;
                        float ni;
                        if (dec0W) {
                            rv += yy * dec0W[j];
                            zv += yy * dec0W[HD + j];
                            ni  = yy * dec0W[2 * HD + j];
                        } else {
                            ni = aNI[mtl][n8][ci] * INVWS;
                        }
                        const float r = 1.f / (1.f + __expf(-(rv + g_br[bt][j])));
                        const float z = 1.f / (1.f + __expf(-(zv + g_bz[bt][j])));
                        const float n = tanhf(ni + g_bin[bt][j] + r * (nh + g_bhn[bt][j]));
                        const float hp = hprev[(size_t)grow * HD + j];
                        const float hv = n + z * (hp - n);
                        hout[(size_t)grow * HD + j] = hv;
                        hq[offel(rloc, kbase + jl)] = __float2half(hv);
                    }
                }
            }
        }
    };

    Ck ckA[9], ckB[8];
    int p = 0;

    // ---------------- encoder: 512 steps ----------------
    for (int t = 0; t < TSEQ; t++) {
        // layer 0: 8 hidden chunks (mode 0) + x chunk (mode 1)
        for (int c = 0; c < 8; c++)
            ckA[c] = { &g_h1h[p][mt][c][0], &g_w[0][nt][c][0][0], 0 };
        ckA[8] = { &g_xh[t][mt][0], &g_wx[nt][0][0], 1 };
        zero_acc();
        run_seg(ckA, 9);
        epilogue(0, g_h1[p], g_h1[1 - p], &g_h1h[1 - p][mt][nt >> 1][0], nullptr);
        // layer 1: hidden GEMM first (old h2), gbar, then input GEMM (new h1)
        for (int c = 0; c < 8; c++) {
            ckA[c] = { &g_h2h[p][mt][c][0], &g_w[2][nt][c][0][0], 0 };
            ckB[c] = { &g_h1h[1 - p][mt][c][0], &g_w[1][nt][c][0][0], 1 };
        }
        zero_acc();
        run_seg(ckA, 8);
        gbar();
        run_seg(ckB, 8);
        epilogue(1, g_h2[p], g_h2[1 - p], &g_h2h[1 - p][mt][nt >> 1][0], nullptr);
        gbar();
        p ^= 1;
    }

    // ---------------- decoder: 96 steps ----------------
    for (int s = 0; s < PLEN; s++) {
        for (int c = 0; c < 8; c++)
            ckA[c] = { &g_h1h[p][mt][c][0], &g_w[3][nt][c][0][0], 0 };
        zero_acc();
        run_seg(ckA, 8);
        epilogue(2, g_h1[p], g_h1[1 - p], &g_h1h[1 - p][mt][nt >> 1][0], dWih0);
        for (int c = 0; c < 8; c++) {
            ckA[c] = { &g_h2h[p][mt][c][0], &g_w[5][nt][c][0][0], 0 };
            ckB[c] = { &g_h1h[1 - p][mt][c][0], &g_w[4][nt][c][0][0], 1 };
        }
        zero_acc();
        run_seg(ckA, 8);
        gbar();
        run_seg(ckB, 8);
        epilogue(3, g_h2[p], g_h2[1 - p], &g_h2h[1 - p][mt][nt >> 1][0], nullptr);
        gbar();
        // projection: 8 rows per CTA, one warp each
        {
            const int row = blockIdx.x * 8 + wid;
            const float* hr = g_h2[1 - p] + (size_t)row * HD;
            float ss = 0.f;
#pragma unroll
            for (int q = 0; q < HD / 32; q++)
                ss += __ldcg(&hr[lane + 32 * q]) * outW[lane + 32 * q];
#pragma unroll
            for (int o = 16; o > 0; o >>= 1)
                ss += __shfl_xor_sync(0xffffffffu, ss, o);
            if (lane == 0) {
                const float v = ss + outb[0];
                g_y[row] = v;
                out[(size_t)row * PLEN + s] = v;
            }
        }
        gbar();
        p ^= 1;
    }
}

// ---------------------------------------------------------------------------
extern "C" void kernel_launch(void* const* d_in, const int* in_sizes, int n_in,
                              void* d_out, int out_size)
{
    const float* x      = (const float*)d_in[0];
    const float* eWih0  = (const float*)d_in[1];
    const float* eWhh0  = (const float*)d_in[2];
    const float* ebih0  = (const float*)d_in[3];
    const float* ebhh0  = (const float*)d_in[4];
    const float* eWih1  = (const float*)d_in[5];
    const float* eWhh1  = (const float*)d_in[6];
    const float* ebih1  = (const float*)d_in[7];
    const float* ebhh1  = (const float*)d_in[8];
    const float* dWih0  = (const float*)d_in[9];
    const float* dWhh0  = (const float*)d_in[10];
    const float* dbih0  = (const float*)d_in[11];
    const float* dbhh0  = (const float*)d_in[12];
    const float* dWih1  = (const float*)d_in[13];
    const float* dWhh1  = (const float*)d_in[14];
    const float* dbih1  = (const float*)d_in[15];
    const float* dbhh1  = (const float*)d_in[16];
    const float* outW   = (const float*)d_in[17];
    const float* outb   = (const float*)d_in[18];
    const float* dstart = (const float*)d_in[19];
    float* out = (float*)d_out;

    cudaFuncSetAttribute(gru_tc, cudaFuncAttributeMaxDynamicSharedMemorySize, SM_TOTAL);

    init_weights<<<1024, 256>>>(eWih0,
                                eWhh0, eWih1, eWhh1, dWhh0, dWih1, dWhh1,
                                ebih0, ebhh0, ebih1, ebhh1,
                                dbih0, dbhh0, dbih1, dbhh1);
    init_x<<<2048, 256>>>(x);
    gru_tc<<<NCTA, 256, SM_TOTAL>>>(dWih0, outW, outb, dstart, out);
}

// round 12
// speedup vs baseline: 3.3508x; 1.0149x over previous
#include <cuda_runtime.h>
#include <cuda_fp16.h>
#include <cstdint>
#include <cstddef>

// ---------------- problem dims ----------------
#define HD    512
#define BATCH 1024
#define TSEQ  512
#define PLEN  96
#define DIN   32

// ---------------- tiling ----------------
#define NCTA 128
#define MT   8          // m-tiles (BATCH/128)
#define NTL  16         // n-tiles (HD/32)
#define BMR  128        // batch rows per CTA
#define KC   64         // k per chunk

#define A_ELE (BMR*KC)      // 8192 halfs
#define A_BYT (A_ELE*2)     // 16384
#define B_HI  (96*KC)       // 6144 halfs (all 3 gates, W_hi)
#define B_LO  (32*KC)       // 2048 halfs (n-gate only, W_lo)
#define B_TOT (B_HI+B_LO)   // 8192 halfs
#define B_BYT (B_TOT*2)     // 16384
#define BUF_BYTES (A_BYT + B_BYT)   // 32768
#define NSTAGE 3
#define SM_TOTAL  (NSTAGE*BUF_BYTES) // 98304

#define WSCALE 1024.f
#define INVWS  (1.f/1024.f)

// ---------------- device globals (static scratch) ----------------
__device__ float g_h1[2][BATCH*HD];
__device__ float g_h2[2][BATCH*HD];
__device__ __align__(16) __half g_h1h[2][MT][8][A_ELE];
__device__ __align__(16) __half g_h2h[2][MT][8][A_ELE];
__device__ __align__(16) __half g_xh[TSEQ][MT][A_ELE];      // [xh(32)|0]
__device__ __align__(16) __half g_w[6][NTL][8][B_TOT];      // x1024; [hi 96x64 | lo(n) 32x64]
__device__ __align__(16) __half g_wx[NTL][B_TOT];           // enc0 Wih x1024, same layout
__device__ float g_br[4][HD], g_bz[4][HD], g_bin[4][HD], g_bhn[4][HD];
__device__ float g_y[BATCH];
__device__ unsigned g_cnt, g_gen;

// ---------------- tile addressing (ldmatrix-friendly swizzle) ----------------
__host__ __device__ __forceinline__ int offel(int r, int k) {
    return r * 64 + ((((k >> 3) ^ (r & 7)) << 3) | (k & 7));
}

// ---------------- PTX helpers ----------------
__device__ __forceinline__ uint32_t smem_u32(const void* p) {
    uint32_t a;
    asm("{ .reg .u64 t; cvta.to.shared.u64 t, %1; cvt.u32.u64 %0, t; }" : "=r"(a) : "l"(p));
    return a;
}
#define LDSM4(r, addr) asm volatile("ldmatrix.sync.aligned.m8n8.x4.shared.b16 {%0,%1,%2,%3},[%4];" \
    : "=r"((r)[0]), "=r"((r)[1]), "=r"((r)[2]), "=r"((r)[3]) : "r"(addr))
#define MMAH(d, a, b0, b1) asm volatile( \
    "mma.sync.aligned.m16n8k16.row.col.f32.f16.f16.f32 {%0,%1,%2,%3},{%4,%5,%6,%7},{%8,%9},{%0,%1,%2,%3};" \
    : "+f"((d)[0]), "+f"((d)[1]), "+f"((d)[2]), "+f"((d)[3]) \
    : "r"((a)[0]), "r"((a)[1]), "r"((a)[2]), "r"((a)[3]), "r"(b0), "r"(b1))
#define CPA16(sa, gp) asm volatile("cp.async.cg.shared.global [%0],[%1],16;" :: "r"(sa), "l"(gp))
#define CPCOMMIT()    asm volatile("cp.async.commit_group;" ::: "memory")
#define CPWAIT1()     asm volatile("cp.async.wait_group 1;" ::: "memory")
#define CPWAIT0()     asm volatile("cp.async.wait_group 0;" ::: "memory")

// ---------------- init kernels ----------------
__global__ void init_weights(
    const float* __restrict__ eWih0,
    const float* __restrict__ eWhh0, const float* __restrict__ eWih1, const float* __restrict__ eWhh1,
    const float* __restrict__ dWhh0, const float* __restrict__ dWih1, const float* __restrict__ dWhh1,
    const float* __restrict__ ebih0, const float* __restrict__ ebhh0,
    const float* __restrict__ ebih1, const float* __restrict__ ebhh1,
    const float* __restrict__ dbih0, const float* __restrict__ dbhh0,
    const float* __restrict__ dbih1, const float* __restrict__ dbhh1)
{
    const float* Wsrc[6] = {eWhh0, eWih1, eWhh1, dWhh0, dWih1, dWhh1};
    const long stride = (long)gridDim.x * blockDim.x;
    const long i0 = (long)blockIdx.x * blockDim.x + threadIdx.x;

    // hi limb: all 96 gate rows; lo limb: only n-gate (rows 64..95)
    const long totW = 6L * NTL * 8 * 96 * KC;
    for (long i = i0; i < totW; i += stride) {
        int k = (int)(i % KC); long q = i / KC;
        int r = (int)(q % 96); q /= 96;
        int ch = (int)(q % 8); q /= 8;
        int nt = (int)(q % NTL); int ty = (int)(q / NTL);
        int g = r >> 5, jl = r & 31, j = nt * 32 + jl, kg = ch * KC + k;
        float v = Wsrc[ty][(size_t)(g * HD + j) * HD + kg] * WSCALE;
        __half hi = __float2half(v);
        g_w[ty][nt][ch][offel(r, k)] = hi;
        if (g == 2)
            g_w[ty][nt][ch][B_HI + offel(jl, k)] = __float2half(v - __half2float(hi));
    }
    // enc0 Wih (K=32): hi [Wh|0] rows 96; lo (n only) [Wl|0] rows 32
    const long totX = (long)NTL * 96 * KC;
    for (long i = i0; i < totX; i += stride) {
        int k = (int)(i % KC); long q = i / KC;
        int r = (int)(q % 96);   int nt = (int)(q / 96);
        int g = r >> 5, jl = r & 31, j = nt * 32 + jl;
        float v = (k < 32) ? eWih0[(size_t)(g * HD + j) * DIN + k] * WSCALE : 0.f;
        __half hi = __float2half(v);
        g_wx[nt][offel(r, k)] = hi;
        if (g == 2)
            g_wx[nt][B_HI + offel(jl, k)] = __float2half(v - __half2float(hi));
    }
    const float* bi[4] = {ebih0, ebih1, dbih0, dbih1};
    const float* bh[4] = {ebhh0, ebhh1, dbhh0, dbhh1};
    for (long i = i0; i < 4 * HD; i += stride) {
        int tt = (int)(i / HD), j = (int)(i % HD);
        g_br[tt][j]  = bi[tt][j] + bh[tt][j];
        g_bz[tt][j]  = bi[tt][HD + j] + bh[tt][HD + j];
        g_bin[tt][j] = bi[tt][2 * HD + j];
        g_bhn[tt][j] = bh[tt][2 * HD + j];
    }
}

__global__ void init_x(const float* __restrict__ x)
{
    const long stride = (long)gridDim.x * blockDim.x;
    const long tot = (long)TSEQ * MT * BMR * KC;
    for (long i = (long)blockIdx.x * blockDim.x + threadIdx.x; i < tot; i += stride) {
        int k = (int)(i % KC); long q = i / KC;
        int r = (int)(q % BMR); q /= BMR;
        int mt = (int)(q % MT); int t = (int)(q / MT);
        __half val = __float2half(0.f);
        if (k < 32) {
            int b = mt * BMR + r;
            val = __float2half(x[((long)b * TSEQ + t) * DIN + k]);
        }
        g_xh[t][mt][offel(r, k)] = val;
    }
}

// ---------------- grid barrier ----------------
__device__ __forceinline__ void gbar()
{
    __syncthreads();
    if (threadIdx.x == 0) {
        __threadfence();
        unsigned gen = *(volatile unsigned*)&g_gen;
        unsigned t = atomicAdd(&g_cnt, 1u);
        if (t == NCTA - 1) {
            *(volatile unsigned*)&g_cnt = 0;
            __threadfence();
            *(volatile unsigned*)&g_gen = gen + 1;
        } else {
            while (*(volatile unsigned*)&g_gen == gen) __nanosleep(32);
        }
        __threadfence();
    }
    __syncthreads();
}

// ---------------- chunk compute: fp16 asymmetric products, 4m x 2n warps ----------------
// r,z: single product A*W_hi. n: A*W_hi + A*W_lo.
// MODE 0: hidden GEMM (n -> aNH). MODE 1: input GEMM (n -> aNI).
template<int MODE>
__device__ __forceinline__ void compute_chunk(
    uint32_t sbuf, int lane, int wm, int wn,
    float (&aR)[2][2][4], float (&aZ)[2][2][4],
    float (&aNH)[2][2][4], float (&aNI)[2][2][4])
{
    const uint32_t sA = sbuf;
    const uint32_t sB = sbuf + A_BYT, sBlo = sB + 2 * B_HI;
    const int a_row = wm * 32 + (lane & 7) + ((lane >> 3) & 1) * 8;
    const int a_kh  = (lane >> 4) * 8;
    const int b_roff = (lane & 7) + ((lane >> 4) & 1) * 8;
    const int b_kh   = ((lane >> 3) & 1) * 8;

#pragma unroll
    for (int kq = 0; kq < 4; kq++) {
        const int kb = kq * 16;
        uint32_t ahi[2][4];
#pragma unroll
        for (int mtl = 0; mtl < 2; mtl++)
            LDSM4(ahi[mtl], sA + 2u * (uint32_t)offel(a_row + mtl * 16, kb + a_kh));
#pragma unroll
        for (int g = 0; g < 3; g++) {
            const int brow = wn * 16 + b_roff;
            uint32_t bhi[4];
            LDSM4(bhi, sB + 2u * (uint32_t)offel(g * 32 + brow, kb + b_kh));
            if (g < 2) {
#pragma unroll
                for (int mtl = 0; mtl < 2; mtl++)
#pragma unroll
                    for (int n8 = 0; n8 < 2; n8++) {
                        float* dst = (g == 0) ? aR[mtl][n8] : aZ[mtl][n8];
                        MMAH(dst, ahi[mtl], bhi[2 * n8], bhi[2 * n8 + 1]);
                    }
            } else {
                uint32_t blo[4];
                LDSM4(blo, sBlo + 2u * (uint32_t)offel(brow, kb + b_kh));
#pragma unroll
                for (int mtl = 0; mtl < 2; mtl++)
#pragma unroll
                    for (int n8 = 0; n8 < 2; n8++) {
                        float* dst = (MODE == 0) ? aNH[mtl][n8] : aNI[mtl][n8];
                        MMAH(dst, ahi[mtl], bhi[2 * n8], bhi[2 * n8 + 1]);
                        MMAH(dst, ahi[mtl], blo[2 * n8], blo[2 * n8 + 1]);
                    }
            }
        }
    }
}

struct Ck { const __half* A; const __half* B; int mode; };

// ---------------- persistent kernel ----------------
__global__ void __launch_bounds__(256, 1) gru_tc(
    const float* __restrict__ dWih0,
    const float* __restrict__ outW, const float* __restrict__ outb,
    const float* __restrict__ dstart, float* __restrict__ out)
{
    extern __shared__ char smem[];
    const int tid = threadIdx.x, wid = tid >> 5, lane = tid & 31;
    const int wm = wid & 3, wn = wid >> 2;
    const int mt = blockIdx.x >> 4, nt = blockIdx.x & 15;

    // ---- per-launch state init ----
    {
        const long gs = (long)NCTA * 256;
        for (long i = (long)blockIdx.x * 256 + tid; i < (long)BATCH * HD; i += gs) {
            g_h1[0][i] = 0.f; g_h2[0][i] = 0.f;
        }
        uint32_t* z1 = (uint32_t*)&g_h1h[0][0][0][0];
        uint32_t* z2 = (uint32_t*)&g_h2h[0][0][0][0];
        const long nz = (long)MT * 8 * A_ELE / 2;
        for (long i = (long)blockIdx.x * 256 + tid; i < nz; i += gs) { z1[i] = 0; z2[i] = 0; }
        for (long i = (long)blockIdx.x * 256 + tid; i < BATCH; i += gs) g_y[i] = dstart[0];
    }
    gbar();

    float aR[2][2][4], aZ[2][2][4], aNH[2][2][4], aNI[2][2][4];

    auto zero_acc = [&]() {
#pragma unroll
        for (int a = 0; a < 2; a++)
#pragma unroll
            for (int b = 0; b < 2; b++)
#pragma unroll
                for (int c = 0; c < 4; c++) {
                    aR[a][b][c] = 0.f; aZ[a][b][c] = 0.f;
                    aNH[a][b][c] = 0.f; aNI[a][b][c] = 0.f;
                }
    };

    auto load_chunk = [&](int buf, const Ck& c) {
        uint32_t dst = smem_u32(smem) + buf * BUF_BYTES;
        const char* A = (const char*)c.A;
        const char* B = (const char*)c.B;
#pragma unroll
        for (int i = 0; i < 4; i++)
            CPA16(dst + (tid + i * 256) * 16, A + (size_t)(tid + i * 256) * 16);
        const uint32_t bdst = dst + A_BYT;
#pragma unroll
        for (int i = 0; i < 4; i++)
            CPA16(bdst + (tid + i * 256) * 16, B + (size_t)(tid + i * 256) * 16);
        CPCOMMIT();
    };

    // 3-stage pipeline: 2 loads in flight, 1 syncthreads per chunk.
    auto run_seg = [&](const Ck* cks, int n) {
        load_chunk(0, cks[0]);
        if (n > 1) load_chunk(1, cks[1]);
        int buf = 0;
        for (int i = 0; i < n; i++) {
            if (i + 1 < n) CPWAIT1(); else CPWAIT0();
            __syncthreads();          // buffer i ready; buffer (i-1)%3 free for reload
            if (i + 2 < n) load_chunk((buf + 2) % NSTAGE, cks[i + 2]);
            const uint32_t sbuf = smem_u32(smem) + buf * BUF_BYTES;
            if (cks[i].mode == 0) compute_chunk<0>(sbuf, lane, wm, wn, aR, aZ, aNH, aNI);
            else                  compute_chunk<1>(sbuf, lane, wm, wn, aR, aZ, aNH, aNI);
            buf = (buf + 1) % NSTAGE;
        }
        __syncthreads();              // protect buffers before next segment's prefetch
    };

    // epilogue: gates + state update. dec0W != null => decoder layer0 scalar input.
    auto epilogue = [&](int bt, const float* hprev, float* hout,
                        __half* hq, const float* dec0W) {
        const int qr = lane >> 2, qc = lane & 3;
        const int kbase = (nt & 1) * 32;
#pragma unroll
        for (int mtl = 0; mtl < 2; mtl++) {
#pragma unroll
            for (int fr = 0; fr < 2; fr++) {
                const int rloc = wm * 32 + mtl * 16 + qr + fr * 8;
                const int grow = mt * 128 + rloc;
                const float yy = dec0W ? __ldcg(&g_y[grow]) : 0.f;
#pragma unroll
                for (int n8 = 0; n8 < 2; n8++) {
#pragma unroll
                    for (int e = 0; e < 2; e++) {
                        const int jl = wn * 16 + n8 * 8 + qc * 2 + e;
                        const int j = nt * 32 + jl;
                        const int ci = fr * 2 + e;
                        float rv = aR[mtl][n8][ci] * INVWS;
                        float zv = aZ[mtl][n8][ci] * INVWS;
                        float nh = aNH[mtl][n8][ci] * INVWS;
                        float ni;
                        if (dec0W) {
                            rv += yy * dec0W[j];
                            zv += yy * dec0W[HD + j];
                            ni  = yy * dec0W[2 * HD + j];
                        } else {
                            ni = aNI[mtl][n8][ci] * INVWS;
                        }
                        const float r = 1.f / (1.f + __expf(-(rv + g_br[bt][j])));
                        const float z = 1.f / (1.f + __expf(-(zv + g_bz[bt][j])));
                        const float n = tanhf(ni + g_bin[bt][j] + r * (nh + g_bhn[bt][j]));
                        const float hp = hprev[(size_t)grow * HD + j];
                        const float hv = n + z * (hp - n);
                        hout[(size_t)grow * HD + j] = hv;
                        hq[offel(rloc, kbase + jl)] = __float2half(hv);
                    }
                }
            }
        }
    };

    Ck ckA[9], ckB[8];
    int p = 0;

    // ---------------- encoder: 512 steps ----------------
    for (int t = 0; t < TSEQ; t++) {
        // layer 0: 8 hidden chunks (mode 0) + x chunk (mode 1)
        for (int c = 0; c < 8; c++)
            ckA[c] = { &g_h1h[p][mt][c][0], &g_w[0][nt][c][0], 0 };
        ckA[8] = { &g_xh[t][mt][0], &g_wx[nt][0], 1 };
        zero_acc();
        run_seg(ckA, 9);
        epilogue(0, g_h1[p], g_h1[1 - p], &g_h1h[1 - p][mt][nt >> 1][0], nullptr);
        // layer 1: hidden GEMM first (old h2), gbar, then input GEMM (new h1)
        for (int c = 0; c < 8; c++) {
            ckA[c] = { &g_h2h[p][mt][c][0], &g_w[2][nt][c][0], 0 };
            ckB[c] = { &g_h1h[1 - p][mt][c][0], &g_w[1][nt][c][0], 1 };
        }
        zero_acc();
        run_seg(ckA, 8);
        gbar();
        run_seg(ckB, 8);
        epilogue(1, g_h2[p], g_h2[1 - p], &g_h2h[1 - p][mt][nt >> 1][0], nullptr);
        gbar();
        p ^= 1;
    }

    // ---------------- decoder: 96 steps ----------------
    for (int s = 0; s < PLEN; s++) {
        for (int c = 0; c < 8; c++)
            ckA[c] = { &g_h1h[p][mt][c][0], &g_w[3][nt][c][0], 0 };
        zero_acc();
        run_seg(ckA, 8);
        epilogue(2, g_h1[p], g_h1[1 - p], &g_h1h[1 - p][mt][nt >> 1][0], dWih0);
        for (int c = 0; c < 8; c++) {
            ckA[c] = { &g_h2h[p][mt][c][0], &g_w[5][nt][c][0], 0 };
            ckB[c] = { &g_h1h[1 - p][mt][c][0], &g_w[4][nt][c][0], 1 };
        }
        zero_acc();
        run_seg(ckA, 8);
        gbar();
        run_seg(ckB, 8);
        epilogue(3, g_h2[p], g_h2[1 - p], &g_h2h[1 - p][mt][nt >> 1][0], nullptr);
        gbar();
        // projection: 8 rows per CTA, one warp each
        {
            const int row = blockIdx.x * 8 + wid;
            const float* hr = g_h2[1 - p] + (size_t)row * HD;
            float ss = 0.f;
#pragma unroll
            for (int q = 0; q < HD / 32; q++)
                ss += __ldcg(&hr[lane + 32 * q]) * outW[lane + 32 * q];
#pragma unroll
            for (int o = 16; o > 0; o >>= 1)
                ss += __shfl_xor_sync(0xffffffffu, ss, o);
            if (lane == 0) {
                const float v = ss + outb[0];
                g_y[row] = v;
                out[(size_t)row * PLEN + s] = v;
            }
        }
        gbar();
        p ^= 1;
    }
}

// ---------------------------------------------------------------------------
extern "C" void kernel_launch(void* const* d_in, const int* in_sizes, int n_in,
                              void* d_out, int out_size)
{
    const float* x      = (const float*)d_in[0];
    const float* eWih0  = (const float*)d_in[1];
    const float* eWhh0  = (const float*)d_in[2];
    const float* ebih0  = (const float*)d_in[3];
    const float* ebhh0  = (const float*)d_in[4];
    const float* eWih1  = (const float*)d_in[5];
    const float* eWhh1  = (const float*)d_in[6];
    const float* ebih1  = (const float*)d_in[7];
    const float* ebhh1  = (const float*)d_in[8];
    const float* dWih0  = (const float*)d_in[9];
    const float* dWhh0  = (const float*)d_in[10];
    const float* dbih0  = (const float*)d_in[11];
    const float* dbhh0  = (const float*)d_in[12];
    const float* dWih1  = (const float*)d_in[13];
    const float* dWhh1  = (const float*)d_in[14];
    const float* dbih1  = (const float*)d_in[15];
    const float* dbhh1  = (const float*)d_in[16];
    const float* outW   = (const float*)d_in[17];
    const float* outb   = (const float*)d_in[18];
    const float* dstart = (const float*)d_in[19];
    float* out = (float*)d_out;

    cudaFuncSetAttribute(gru_tc, cudaFuncAttributeMaxDynamicSharedMemorySize, SM_TOTAL);

    init_weights<<<1024, 256>>>(eWih0,
                                eWhh0, eWih1, eWhh1, dWhh0, dWih1, dWhh1,
                                ebih0, ebhh0, ebih1, ebhh1,
                                dbih0, dbhh0, dbih1, dbhh1);
    init_x<<<2048, 256>>>(x);
    gru_tc<<<NCTA, 256, SM_TOTAL>>>(dWih0, outW, outb, dstart, out);
}

// round 13
// speedup vs baseline: 3.6078x; 1.0767x over previous
#include <cuda_runtime.h>
#include <cuda_fp16.h>
#include <cstdint>
#include <cstddef>

// ---------------- problem dims ----------------
#define HD    512
#define BATCH 1024
#define TSEQ  512
#define PLEN  96
#define DIN   32

// ---------------- tiling ----------------
#define NCTA 128
#define MT   8          // m-tiles (BATCH/128)
#define NTL  16         // n-tiles (HD/32)
#define BMR  128        // batch rows per CTA
#define KC   64         // k per chunk

#define A_ELE (BMR*KC)      // 8192 halfs
#define A_BYT (A_ELE*2)     // 16384
#define B_HI  (96*KC)       // 6144 halfs (3 gates, W_hi only)
#define B_BYT (B_HI*2)      // 12288
#define BUF_BYTES (A_BYT + B_BYT)    // 28672
#define NSTAGE 3
#define SM_TOTAL  (NSTAGE*BUF_BYTES) // 86016

#define WSCALE 1024.f
#define INVWS  (1.f/1024.f)

// ---------------- device globals (static scratch) ----------------
__device__ float g_h1[2][BATCH*HD];
__device__ float g_h2[2][BATCH*HD];
__device__ __align__(16) __half g_h1h[2][MT][8][A_ELE];
__device__ __align__(16) __half g_h2h[2][MT][8][A_ELE];
__device__ __align__(16) __half g_xh[TSEQ][MT][A_ELE];   // [xh(32)|0]
__device__ __align__(16) __half g_w[6][NTL][8][B_HI];    // x1024 W_hi; 0:e0hh 1:e1ih 2:e1hh 3:d0hh 4:d1ih 5:d1hh
__device__ __align__(16) __half g_wx[NTL][B_HI];         // enc0 Wih x1024: [Wh(32)|0]
__device__ float g_br[4][HD], g_bz[4][HD], g_bin[4][HD], g_bhn[4][HD];
__device__ float g_y[BATCH];
__device__ unsigned g_cnt, g_gen;

// ---------------- tile addressing (ldmatrix-friendly swizzle) ----------------
__host__ __device__ __forceinline__ int offel(int r, int k) {
    return r * 64 + ((((k >> 3) ^ (r & 7)) << 3) | (k & 7));
}

// ---------------- PTX helpers ----------------
__device__ __forceinline__ uint32_t smem_u32(const void* p) {
    uint32_t a;
    asm("{ .reg .u64 t; cvta.to.shared.u64 t, %1; cvt.u32.u64 %0, t; }" : "=r"(a) : "l"(p));
    return a;
}
#define LDSM4(r, addr) asm volatile("ldmatrix.sync.aligned.m8n8.x4.shared.b16 {%0,%1,%2,%3},[%4];" \
    : "=r"((r)[0]), "=r"((r)[1]), "=r"((r)[2]), "=r"((r)[3]) : "r"(addr))
#define MMAH(d, a, b0, b1) asm volatile( \
    "mma.sync.aligned.m16n8k16.row.col.f32.f16.f16.f32 {%0,%1,%2,%3},{%4,%5,%6,%7},{%8,%9},{%0,%1,%2,%3};" \
    : "+f"((d)[0]), "+f"((d)[1]), "+f"((d)[2]), "+f"((d)[3]) \
    : "r"((a)[0]), "r"((a)[1]), "r"((a)[2]), "r"((a)[3]), "r"(b0), "r"(b1))
#define CPA16(sa, gp) asm volatile("cp.async.cg.shared.global [%0],[%1],16;" :: "r"(sa), "l"(gp))
#define CPCOMMIT()    asm volatile("cp.async.commit_group;" ::: "memory")
#define CPWAIT1()     asm volatile("cp.async.wait_group 1;" ::: "memory")
#define CPWAIT0()     asm volatile("cp.async.wait_group 0;" ::: "memory")

// ---------------- init kernels ----------------
__global__ void init_weights(
    const float* __restrict__ eWih0,
    const float* __restrict__ eWhh0, const float* __restrict__ eWih1, const float* __restrict__ eWhh1,
    const float* __restrict__ dWhh0, const float* __restrict__ dWih1, const float* __restrict__ dWhh1,
    const float* __restrict__ ebih0, const float* __restrict__ ebhh0,
    const float* __restrict__ ebih1, const float* __restrict__ ebhh1,
    const float* __restrict__ dbih0, const float* __restrict__ dbhh0,
    const float* __restrict__ dbih1, const float* __restrict__ dbhh1)
{
    const float* Wsrc[6] = {eWhh0, eWih1, eWhh1, dWhh0, dWih1, dWhh1};
    const long stride = (long)gridDim.x * blockDim.x;
    const long i0 = (long)blockIdx.x * blockDim.x + threadIdx.x;

    const long totW = 6L * NTL * 8 * 96 * KC;
    for (long i = i0; i < totW; i += stride) {
        int k = (int)(i % KC); long q = i / KC;
        int r = (int)(q % 96); q /= 96;
        int ch = (int)(q % 8); q /= 8;
        int nt = (int)(q % NTL); int ty = (int)(q / NTL);
        int g = r >> 5, jl = r & 31, j = nt * 32 + jl, kg = ch * KC + k;
        float v = Wsrc[ty][(size_t)(g * HD + j) * HD + kg] * WSCALE;
        g_w[ty][nt][ch][offel(r, k)] = __float2half(v);
    }
    // enc0 Wih (K=32): [Wh|0]
    const long totX = (long)NTL * 96 * KC;
    for (long i = i0; i < totX; i += stride) {
        int k = (int)(i % KC); long q = i / KC;
        int r = (int)(q % 96);   int nt = (int)(q / 96);
        int g = r >> 5, jl = r & 31, j = nt * 32 + jl;
        float v = (k < 32) ? eWih0[(size_t)(g * HD + j) * DIN + k] * WSCALE : 0.f;
        g_wx[nt][offel(r, k)] = __float2half(v);
    }
    const float* bi[4] = {ebih0, ebih1, dbih0, dbih1};
    const float* bh[4] = {ebhh0, ebhh1, dbhh0, dbhh1};
    for (long i = i0; i < 4 * HD; i += stride) {
        int tt = (int)(i / HD), j = (int)(i % HD);
        g_br[tt][j]  = bi[tt][j] + bh[tt][j];
        g_bz[tt][j]  = bi[tt][HD + j] + bh[tt][HD + j];
        g_bin[tt][j] = bi[tt][2 * HD + j];
        g_bhn[tt][j] = bh[tt][2 * HD + j];
    }
}

__global__ void init_x(const float* __restrict__ x)
{
    const long stride = (long)gridDim.x * blockDim.x;
    const long tot = (long)TSEQ * MT * BMR * KC;
    for (long i = (long)blockIdx.x * blockDim.x + threadIdx.x; i < tot; i += stride) {
        int k = (int)(i % KC); long q = i / KC;
        int r = (int)(q % BMR); q /= BMR;
        int mt = (int)(q % MT); int t = (int)(q / MT);
        __half val = __float2half(0.f);
        if (k < 32) {
            int b = mt * BMR + r;
            val = __float2half(x[((long)b * TSEQ + t) * DIN + k]);
        }
        g_xh[t][mt][offel(r, k)] = val;
    }
}

// ---------------- grid barrier ----------------
__device__ __forceinline__ void gbar()
{
    __syncthreads();
    if (threadIdx.x == 0) {
        __threadfence();
        unsigned gen = *(volatile unsigned*)&g_gen;
        unsigned t = atomicAdd(&g_cnt, 1u);
        if (t == NCTA - 1) {
            *(volatile unsigned*)&g_cnt = 0;
            __threadfence();
            *(volatile unsigned*)&g_gen = gen + 1;
        } else {
            while (*(volatile unsigned*)&g_gen == gen) __nanosleep(32);
        }
        __threadfence();
    }
    __syncthreads();
}

// ---------------- chunk compute: fp16 single product, 4m x 2n warps ----------------
// All gates: one product A*W_hi. MODE 0: n -> aNH. MODE 1: n -> aNI.
template<int MODE>
__device__ __forceinline__ void compute_chunk(
    uint32_t sbuf, int lane, int wm, int wn,
    float (&aR)[2][2][4], float (&aZ)[2][2][4],
    float (&aNH)[2][2][4], float (&aNI)[2][2][4])
{
    const uint32_t sA = sbuf;
    const uint32_t sB = sbuf + A_BYT;
    const int a_row = wm * 32 + (lane & 7) + ((lane >> 3) & 1) * 8;
    const int a_kh  = (lane >> 4) * 8;
    const int b_roff = (lane & 7) + ((lane >> 4) & 1) * 8;
    const int b_kh   = ((lane >> 3) & 1) * 8;

#pragma unroll
    for (int kq = 0; kq < 4; kq++) {
        const int kb = kq * 16;
        uint32_t ahi[2][4];
#pragma unroll
        for (int mtl = 0; mtl < 2; mtl++)
            LDSM4(ahi[mtl], sA + 2u * (uint32_t)offel(a_row + mtl * 16, kb + a_kh));
#pragma unroll
        for (int g = 0; g < 3; g++) {
            uint32_t bhi[4];
            LDSM4(bhi, sB + 2u * (uint32_t)offel(g * 32 + wn * 16 + b_roff, kb + b_kh));
#pragma unroll
            for (int mtl = 0; mtl < 2; mtl++)
#pragma unroll
                for (int n8 = 0; n8 < 2; n8++) {
                    float* dst = (g == 0) ? aR[mtl][n8]
                               : (g == 1) ? aZ[mtl][n8]
                               : (MODE == 0 ? aNH[mtl][n8] : aNI[mtl][n8]);
                    MMAH(dst, ahi[mtl], bhi[2 * n8], bhi[2 * n8 + 1]);
                }
        }
    }
}

struct Ck { const __half* A; const __half* B; int mode; };

// ---------------- persistent kernel ----------------
__global__ void __launch_bounds__(256, 1) gru_tc(
    const float* __restrict__ dWih0,
    const float* __restrict__ outW, const float* __restrict__ outb,
    const float* __restrict__ dstart, float* __restrict__ out)
{
    extern __shared__ char smem[];
    const int tid = threadIdx.x, wid = tid >> 5, lane = tid & 31;
    const int wm = wid & 3, wn = wid >> 2;
    const int mt = blockIdx.x >> 4, nt = blockIdx.x & 15;

    // ---- per-launch state init ----
    {
        const long gs = (long)NCTA * 256;
        for (long i = (long)blockIdx.x * 256 + tid; i < (long)BATCH * HD; i += gs) {
            g_h1[0][i] = 0.f; g_h2[0][i] = 0.f;
        }
        uint32_t* z1 = (uint32_t*)&g_h1h[0][0][0][0];
        uint32_t* z2 = (uint32_t*)&g_h2h[0][0][0][0];
        const long nz = (long)MT * 8 * A_ELE / 2;
        for (long i = (long)blockIdx.x * 256 + tid; i < nz; i += gs) { z1[i] = 0; z2[i] = 0; }
        for (long i = (long)blockIdx.x * 256 + tid; i < BATCH; i += gs) g_y[i] = dstart[0];
    }
    gbar();

    float aR[2][2][4], aZ[2][2][4], aNH[2][2][4], aNI[2][2][4];

    auto zero_acc = [&]() {
#pragma unroll
        for (int a = 0; a < 2; a++)
#pragma unroll
            for (int b = 0; b < 2; b++)
#pragma unroll
                for (int c = 0; c < 4; c++) {
                    aR[a][b][c] = 0.f; aZ[a][b][c] = 0.f;
                    aNH[a][b][c] = 0.f; aNI[a][b][c] = 0.f;
                }
    };

    auto load_chunk = [&](int buf, const Ck& c) {
        uint32_t dst = smem_u32(smem) + buf * BUF_BYTES;
        const char* A = (const char*)c.A;
        const char* B = (const char*)c.B;
#pragma unroll
        for (int i = 0; i < 4; i++)
            CPA16(dst + (tid + i * 256) * 16, A + (size_t)(tid + i * 256) * 16);
        const uint32_t bdst = dst + A_BYT;
#pragma unroll
        for (int i = 0; i < 3; i++)
            CPA16(bdst + (tid + i * 256) * 16, B + (size_t)(tid + i * 256) * 16);
        CPCOMMIT();
    };

    // 3-stage pipeline: 2 loads in flight, 1 syncthreads per chunk.
    auto run_seg = [&](const Ck* cks, int n) {
        load_chunk(0, cks[0]);
        if (n > 1) load_chunk(1, cks[1]);
        int buf = 0;
        for (int i = 0; i < n; i++) {
            if (i + 1 < n) CPWAIT1(); else CPWAIT0();
            __syncthreads();
            if (i + 2 < n) load_chunk((buf + 2) % NSTAGE, cks[i + 2]);
            const uint32_t sbuf = smem_u32(smem) + buf * BUF_BYTES;
            if (cks[i].mode == 0) compute_chunk<0>(sbuf, lane, wm, wn, aR, aZ, aNH, aNI);
            else                  compute_chunk<1>(sbuf, lane, wm, wn, aR, aZ, aNH, aNI);
            buf = (buf + 1) % NSTAGE;
        }
        __syncthreads();
    };

    // epilogue: gates + state update. dec0W != null => decoder layer0 scalar input.
    auto epilogue = [&](int bt, const float* hprev, float* hout,
                        __half* hq, const float* dec0W) {
        const int qr = lane >> 2, qc = lane & 3;
        const int kbase = (nt & 1) * 32;
#pragma unroll
        for (int mtl = 0; mtl < 2; mtl++) {
#pragma unroll
            for (int fr = 0; fr < 2; fr++) {
                const int rloc = wm * 32 + mtl * 16 + qr + fr * 8;
                const int grow = mt * 128 + rloc;
                const float yy = dec0W ? __ldcg(&g_y[grow]) : 0.f;
#pragma unroll
                for (int n8 = 0; n8 < 2; n8++) {
#pragma unroll
                    for (int e = 0; e < 2; e++) {
                        const int jl = wn * 16 + n8 * 8 + qc * 2 + e;
                        const int j = nt * 32 + jl;
                        const int ci = fr * 2 + e;
                        float rv = aR[mtl][n8][ci] * INVWS;
                        float zv = aZ[mtl][n8][ci] * INVWS;
                        float nh = aNH[mtl][n8][ci] * INVWS;
                        float ni;
                        if (dec0W) {
                            rv += yy * dec0W[j];
                            zv += yy * dec0W[HD + j];
                            ni  = yy * dec0W[2 * HD + j];
                        } else {
                            ni = aNI[mtl][n8][ci] * INVWS;
                        }
                        const float r = 1.f / (1.f + __expf(-(rv + g_br[bt][j])));
                        const float z = 1.f / (1.f + __expf(-(zv + g_bz[bt][j])));
                        const float n = tanhf(ni + g_bin[bt][j] + r * (nh + g_bhn[bt][j]));
                        const float hp = hprev[(size_t)grow * HD + j];
                        const float hv = n + z * (hp - n);
                        hout[(size_t)grow * HD + j] = hv;
                        hq[offel(rloc, kbase + jl)] = __float2half(hv);
                    }
                }
            }
        }
    };

    Ck ckA[9], ckB[8];
    int p = 0;

    // ---------------- encoder: 512 steps ----------------
    for (int t = 0; t < TSEQ; t++) {
        // layer 0: 8 hidden chunks (mode 0) + x chunk (mode 1)
        for (int c = 0; c < 8; c++)
            ckA[c] = { &g_h1h[p][mt][c][0], &g_w[0][nt][c][0], 0 };
        ckA[8] = { &g_xh[t][mt][0], &g_wx[nt][0], 1 };
        zero_acc();
        run_seg(ckA, 9);
        epilogue(0, g_h1[p], g_h1[1 - p], &g_h1h[1 - p][mt][nt >> 1][0], nullptr);
        // layer 1: hidden GEMM first (old h2), gbar, then input GEMM (new h1)
        for (int c = 0; c < 8; c++) {
            ckA[c] = { &g_h2h[p][mt][c][0], &g_w[2][nt][c][0], 0 };
            ckB[c] = { &g_h1h[1 - p][mt][c][0], &g_w[1][nt][c][0], 1 };
        }
        zero_acc();
        run_seg(ckA, 8);
        gbar();
        run_seg(ckB, 8);
        epilogue(1, g_h2[p], g_h2[1 - p], &g_h2h[1 - p][mt][nt >> 1][0], nullptr);
        gbar();
        p ^= 1;
    }

    // ---------------- decoder: 96 steps ----------------
    for (int s = 0; s < PLEN; s++) {
        for (int c = 0; c < 8; c++)
            ckA[c] = { &g_h1h[p][mt][c][0], &g_w[3][nt][c][0], 0 };
        zero_acc();
        run_seg(ckA, 8);
        epilogue(2, g_h1[p], g_h1[1 - p], &g_h1h[1 - p][mt][nt >> 1][0], dWih0);
        for (int c = 0; c < 8; c++) {
            ckA[c] = { &g_h2h[p][mt][c][0], &g_w[5][nt][c][0], 0 };
            ckB[c] = { &g_h1h[1 - p][mt][c][0], &g_w[4][nt][c][0], 1 };
        }
        zero_acc();
        run_seg(ckA, 8);
        gbar();
        run_seg(ckB, 8);
        epilogue(3, g_h2[p], g_h2[1 - p], &g_h2h[1 - p][mt][nt >> 1][0], nullptr);
        gbar();
        // projection: 8 rows per CTA, one warp each
        {
            const int row = blockIdx.x * 8 + wid;
            const float* hr = g_h2[1 - p] + (size_t)row * HD;
            float ss = 0.f;
#pragma unroll
            for (int q = 0; q < HD / 32; q++)
                ss += __ldcg(&hr[lane + 32 * q]) * outW[lane + 32 * q];
#pragma unroll
            for (int o = 16; o > 0; o >>= 1)
                ss += __shfl_xor_sync(0xffffffffu, ss, o);
            if (lane == 0) {
                const float v = ss + outb[0];
                g_y[row] = v;
                out[(size_t)row * PLEN + s] = v;
            }
        }
        gbar();
        p ^= 1;
    }
}

// ---------------------------------------------------------------------------
extern "C" void kernel_launch(void* const* d_in, const int* in_sizes, int n_in,
                              void* d_out, int out_size)
{
    const float* x      = (const float*)d_in[0];
    const float* eWih0  = (const float*)d_in[1];
    const float* eWhh0  = (const float*)d_in[2];
    const float* ebih0  = (const float*)d_in[3];
    const float* ebhh0  = (const float*)d_in[4];
    const float* eWih1  = (const float*)d_in[5];
    const float* eWhh1  = (const float*)d_in[6];
    const float* ebih1  = (const float*)d_in[7];
    const float* ebhh1  = (const float*)d_in[8];
    const float* dWih0  = (const float*)d_in[9];
    const float* dWhh0  = (const float*)d_in[10];
    const float* dbih0  = (const float*)d_in[11];
    const float* dbhh0  = (const float*)d_in[12];
    const float* dWih1  = (const float*)d_in[13];
    const float* dWhh1  = (const float*)d_in[14];
    const float* dbih1  = (const float*)d_in[15];
    const float* dbhh1  = (const float*)d_in[16];
    const float* outW   = (const float*)d_in[17];
    const float* outb   = (const float*)d_in[18];
    const float* dstart = (const float*)d_in[19];
    float* out = (float*)d_out;

    cudaFuncSetAttribute(gru_tc, cudaFuncAttributeMaxDynamicSharedMemorySize, SM_TOTAL);

    init_weights<<<1024, 256>>>(eWih0,
                                eWhh0, eWih1, eWhh1, dWhh0, dWih1, dWhh1,
                                ebih0, ebhh0, ebih1, ebhh1,
                                dbih0, dbhh0, dbih1, dbhh1);
    init_x<<<2048, 256>>>(x);
    gru_tc<<<NCTA, 256, SM_TOTAL>>>(dWih0, outW, outb, dstart, out);
}

// round 14
// speedup vs baseline: 3.7868x; 1.0496x over previous
#include <cuda_runtime.h>
#include <cuda_fp16.h>
#include <cstdint>
#include <cstddef>

// ---------------- problem dims ----------------
#define HD    512
#define BATCH 1024
#define TSEQ  512
#define PLEN  96
#define DIN   32

// ---------------- tiling ----------------
#define NCTA 128
#define MT   8
#define NTL  16
#define BMR  128
#define KC   64

#define A_ELE (BMR*KC)      // 8192 halfs
#define A_BYT (A_ELE*2)     // 16384
#define B_HI  (96*KC)       // 6144 halfs
#define B_BYT (B_HI*2)      // 12288
#define BUF_BYTES (A_BYT + B_BYT)    // 28672
#define NSTAGE 3
#define SM_TOTAL  (NSTAGE*BUF_BYTES) // 86016

#define WSCALE 1024.f
#define INVWS  (1.f/1024.f)

// ---------------- device globals ----------------
__device__ float g_h1[2][BATCH*HD];
__device__ float g_h2[2][BATCH*HD];
__device__ __align__(16) __half g_h1h[2][MT][8][A_ELE];
__device__ __align__(16) __half g_h2h[2][MT][8][A_ELE];
__device__ __align__(16) __half g_xh[TSEQ][MT][A_ELE];
__device__ __align__(16) __half g_w[6][NTL][8][B_HI];   // 0:e0hh 1:e1ih 2:e1hh 3:d0hh 4:d1ih 5:d1hh
__device__ __align__(16) __half g_wx[NTL][B_HI];
__device__ float g_br[4][HD], g_bz[4][HD], g_bin[4][HD], g_bhn[4][HD];
__device__ float g_y[BATCH];
__device__ unsigned g_cnt, g_gen;
__device__ unsigned g_ph[8];   // split-barrier slots (reset each launch)

// ---------------- tile addressing ----------------
__host__ __device__ __forceinline__ int offel(int r, int k) {
    return r * 64 + ((((k >> 3) ^ (r & 7)) << 3) | (k & 7));
}

// ---------------- PTX helpers ----------------
__device__ __forceinline__ uint32_t smem_u32(const void* p) {
    uint32_t a;
    asm("{ .reg .u64 t; cvta.to.shared.u64 t, %1; cvt.u32.u64 %0, t; }" : "=r"(a) : "l"(p));
    return a;
}
#define LDSM4(r, addr) asm volatile("ldmatrix.sync.aligned.m8n8.x4.shared.b16 {%0,%1,%2,%3},[%4];" \
    : "=r"((r)[0]), "=r"((r)[1]), "=r"((r)[2]), "=r"((r)[3]) : "r"(addr))
#define MMAH(d, a, b0, b1) asm volatile( \
    "mma.sync.aligned.m16n8k16.row.col.f32.f16.f16.f32 {%0,%1,%2,%3},{%4,%5,%6,%7},{%8,%9},{%0,%1,%2,%3};" \
    : "+f"((d)[0]), "+f"((d)[1]), "+f"((d)[2]), "+f"((d)[3]) \
    : "r"((a)[0]), "r"((a)[1]), "r"((a)[2]), "r"((a)[3]), "r"(b0), "r"(b1))
#define CPA16(sa, gp) asm volatile("cp.async.cg.shared.global [%0],[%1],16;" :: "r"(sa), "l"(gp))
#define CPCOMMIT()    asm volatile("cp.async.commit_group;" ::: "memory")
#define CPWAIT1()     asm volatile("cp.async.wait_group 1;" ::: "memory")
#define CPWAIT0()     asm volatile("cp.async.wait_group 0;" ::: "memory")

// ---------------- init kernels ----------------
__global__ void init_weights(
    const float* __restrict__ eWih0,
    const float* __restrict__ eWhh0, const float* __restrict__ eWih1, const float* __restrict__ eWhh1,
    const float* __restrict__ dWhh0, const float* __restrict__ dWih1, const float* __restrict__ dWhh1,
    const float* __restrict__ ebih0, const float* __restrict__ ebhh0,
    const float* __restrict__ ebih1, const float* __restrict__ ebhh1,
    const float* __restrict__ dbih0, const float* __restrict__ dbhh0,
    const float* __restrict__ dbih1, const float* __restrict__ dbhh1)
{
    const float* Wsrc[6] = {eWhh0, eWih1, eWhh1, dWhh0, dWih1, dWhh1};
    const long stride = (long)gridDim.x * blockDim.x;
    const long i0 = (long)blockIdx.x * blockDim.x + threadIdx.x;

    const long totW = 6L * NTL * 8 * 96 * KC;
    for (long i = i0; i < totW; i += stride) {
        int k = (int)(i % KC); long q = i / KC;
        int r = (int)(q % 96); q /= 96;
        int ch = (int)(q % 8); q /= 8;
        int nt = (int)(q % NTL); int ty = (int)(q / NTL);
        int g = r >> 5, jl = r & 31, j = nt * 32 + jl, kg = ch * KC + k;
        float v = Wsrc[ty][(size_t)(g * HD + j) * HD + kg] * WSCALE;
        g_w[ty][nt][ch][offel(r, k)] = __float2half(v);
    }
    const long totX = (long)NTL * 96 * KC;
    for (long i = i0; i < totX; i += stride) {
        int k = (int)(i % KC); long q = i / KC;
        int r = (int)(q % 96);   int nt = (int)(q / 96);
        int g = r >> 5, jl = r & 31, j = nt * 32 + jl;
        float v = (k < 32) ? eWih0[(size_t)(g * HD + j) * DIN + k] * WSCALE : 0.f;
        g_wx[nt][offel(r, k)] = __float2half(v);
    }
    const float* bi[4] = {ebih0, ebih1, dbih0, dbih1};
    const float* bh[4] = {ebhh0, ebhh1, dbhh0, dbhh1};
    for (long i = i0; i < 4 * HD; i += stride) {
        int tt = (int)(i / HD), j = (int)(i % HD);
        g_br[tt][j]  = bi[tt][j] + bh[tt][j];
        g_bz[tt][j]  = bi[tt][HD + j] + bh[tt][HD + j];
        g_bin[tt][j] = bi[tt][2 * HD + j];
        g_bhn[tt][j] = bh[tt][2 * HD + j];
    }
}

__global__ void init_x(const float* __restrict__ x)
{
    const long stride = (long)gridDim.x * blockDim.x;
    const long tot = (long)TSEQ * MT * BMR * KC;
    for (long i = (long)blockIdx.x * blockDim.x + threadIdx.x; i < tot; i += stride) {
        int k = (int)(i % KC); long q = i / KC;
        int r = (int)(q % BMR); q /= BMR;
        int mt = (int)(q % MT); int t = (int)(q / MT);
        __half val = __float2half(0.f);
        if (k < 32) {
            int b = mt * BMR + r;
            val = __float2half(x[((long)b * TSEQ + t) * DIN + k]);
        }
        g_xh[t][mt][offel(r, k)] = val;
    }
}

// ---------------- barriers ----------------
__device__ __forceinline__ void gbar()
{
    __syncthreads();
    if (threadIdx.x == 0) {
        __threadfence();
        unsigned gen = *(volatile unsigned*)&g_gen;
        unsigned t = atomicAdd(&g_cnt, 1u);
        if (t == NCTA - 1) {
            *(volatile unsigned*)&g_cnt = 0;
            __threadfence();
            *(volatile unsigned*)&g_gen = gen + 1;
        } else {
            while (*(volatile unsigned*)&g_gen == gen) __nanosleep(32);
        }
        __threadfence();
    }
    __syncthreads();
}
// Split barrier: monotonic counters, slot = ph&7, target = ((ph>>3)+1)*NCTA.
__device__ __forceinline__ void arriveph(int ph)
{
    __syncthreads();                 // all threads' prior writes done
    if (threadIdx.x == 0) { __threadfence(); atomicAdd(&g_ph[ph & 7], 1u); }
}
__device__ __forceinline__ void waitph(int ph)
{
    __syncthreads();
    if (threadIdx.x == 0) {
        const unsigned target = ((unsigned)(ph >> 3) + 1u) * NCTA;
        while (*(volatile unsigned*)&g_ph[ph & 7] < target) __nanosleep(32);
        __threadfence();
    }
    __syncthreads();
}

// ---------------- chunk compute ----------------
template<int MODE>
__device__ __forceinline__ void compute_chunk(
    uint32_t sbuf, int lane, int wm, int wn,
    float (&aR)[2][2][4], float (&aZ)[2][2][4],
    float (&aNH)[2][2][4], float (&aNI)[2][2][4])
{
    const uint32_t sA = sbuf;
    const uint32_t sB = sbuf + A_BYT;
    const int a_row = wm * 32 + (lane & 7) + ((lane >> 3) & 1) * 8;
    const int a_kh  = (lane >> 4) * 8;
    const int b_roff = (lane & 7) + ((lane >> 4) & 1) * 8;
    const int b_kh   = ((lane >> 3) & 1) * 8;

#pragma unroll
    for (int kq = 0; kq < 4; kq++) {
        const int kb = kq * 16;
        uint32_t ahi[2][4];
#pragma unroll
        for (int mtl = 0; mtl < 2; mtl++)
            LDSM4(ahi[mtl], sA + 2u * (uint32_t)offel(a_row + mtl * 16, kb + a_kh));
#pragma unroll
        for (int g = 0; g < 3; g++) {
            uint32_t bhi[4];
            LDSM4(bhi, sB + 2u * (uint32_t)offel(g * 32 + wn * 16 + b_roff, kb + b_kh));
#pragma unroll
            for (int mtl = 0; mtl < 2; mtl++)
#pragma unroll
                for (int n8 = 0; n8 < 2; n8++) {
                    float* dst = (g == 0) ? aR[mtl][n8]
                               : (g == 1) ? aZ[mtl][n8]
                               : (MODE == 0 ? aNH[mtl][n8] : aNI[mtl][n8]);
                    MMAH(dst, ahi[mtl], bhi[2 * n8], bhi[2 * n8 + 1]);
                }
        }
    }
}

struct Ck { const __half* A; const __half* B; int mode; };

// ---------------- persistent kernel ----------------
__global__ void __launch_bounds__(256, 1) gru_tc(
    const float* __restrict__ dWih0,
    const float* __restrict__ outW, const float* __restrict__ outb,
    const float* __restrict__ dstart, float* __restrict__ out)
{
    extern __shared__ char smem[];
    const int tid = threadIdx.x, wid = tid >> 5, lane = tid & 31;
    const int wm = wid & 3, wn = wid >> 2;
    const int mt = blockIdx.x >> 4, nt = blockIdx.x & 15;

    // ---- per-launch state init (replay-deterministic) ----
    {
        const long gs = (long)NCTA * 256;
        for (long i = (long)blockIdx.x * 256 + tid; i < (long)BATCH * HD; i += gs) {
            g_h1[0][i] = 0.f; g_h2[0][i] = 0.f;
        }
        uint32_t* z1 = (uint32_t*)&g_h1h[0][0][0][0];
        uint32_t* z2 = (uint32_t*)&g_h2h[0][0][0][0];
        const long nz = (long)MT * 8 * A_ELE / 2;
        for (long i = (long)blockIdx.x * 256 + tid; i < nz; i += gs) { z1[i] = 0; z2[i] = 0; }
        for (long i = (long)blockIdx.x * 256 + tid; i < BATCH; i += gs) g_y[i] = dstart[0];
        if (blockIdx.x == 0 && tid < 8) g_ph[tid] = 0;   // reset split-barrier slots
    }
    gbar();

    float aR[2][2][4], aZ[2][2][4], aNH[2][2][4], aNI[2][2][4];

    auto zero_acc = [&]() {
#pragma unroll
        for (int a = 0; a < 2; a++)
#pragma unroll
            for (int b = 0; b < 2; b++)
#pragma unroll
                for (int c = 0; c < 4; c++) {
                    aR[a][b][c] = 0.f; aZ[a][b][c] = 0.f;
                    aNH[a][b][c] = 0.f; aNI[a][b][c] = 0.f;
                }
    };

    auto load_chunk = [&](int buf, const Ck& c) {
        uint32_t dst = smem_u32(smem) + buf * BUF_BYTES;
        const char* A = (const char*)c.A;
        const char* B = (const char*)c.B;
#pragma unroll
        for (int i = 0; i < 4; i++)
            CPA16(dst + (tid + i * 256) * 16, A + (size_t)(tid + i * 256) * 16);
        const uint32_t bdst = dst + A_BYT;
#pragma unroll
        for (int i = 0; i < 3; i++)
            CPA16(bdst + (tid + i * 256) * 16, B + (size_t)(tid + i * 256) * 16);
        CPCOMMIT();
    };

    auto load2 = [&](const Ck* cks) { load_chunk(0, cks[0]); load_chunk(1, cks[1]); };

    // Segment with buffers 0,1 already loading.
    auto run_seg_pre = [&](const Ck* cks, int n) {
        int buf = 0;
        for (int i = 0; i < n; i++) {
            if (i + 1 < n) CPWAIT1(); else CPWAIT0();
            __syncthreads();
            if (i + 2 < n) load_chunk((buf + 2) % NSTAGE, cks[i + 2]);
            const uint32_t sbuf = smem_u32(smem) + buf * BUF_BYTES;
            if (cks[i].mode == 0) compute_chunk<0>(sbuf, lane, wm, wn, aR, aZ, aNH, aNI);
            else                  compute_chunk<1>(sbuf, lane, wm, wn, aR, aZ, aNH, aNI);
            buf = (buf + 1) % NSTAGE;
        }
        __syncthreads();
    };

    // Merged layer-1: 8 hidden chunks (mode0) + 8 input chunks (mode1), one
    // pipeline; wait(phA) issued exactly before the first input-chunk load.
    auto run_l1 = [&](const Ck* cka, const Ck* ckb, int phA) {
        int buf = 0;
        for (int i = 0; i < 16; i++) {
            if (i + 1 < 16) CPWAIT1(); else CPWAIT0();
            __syncthreads();
            if (i + 2 < 16) {
                if (i + 2 == 8) waitph(phA);   // h1h[1-p] ready before its first load
                const Ck& c = (i + 2 < 8) ? cka[i + 2] : ckb[i - 6];
                load_chunk((buf + 2) % NSTAGE, c);
            }
            const uint32_t sbuf = smem_u32(smem) + buf * BUF_BYTES;
            if (i < 8) compute_chunk<0>(sbuf, lane, wm, wn, aR, aZ, aNH, aNI);
            else       compute_chunk<1>(sbuf, lane, wm, wn, aR, aZ, aNH, aNI);
            buf = (buf + 1) % NSTAGE;
        }
        __syncthreads();
    };

    auto epilogue = [&](int bt, const float* hprev, float* hout,
                        __half* hq, const float* dec0W) {
        const int qr = lane >> 2, qc = lane & 3;
        const int kbase = (nt & 1) * 32;
#pragma unroll
        for (int mtl = 0; mtl < 2; mtl++) {
#pragma unroll
            for (int fr = 0; fr < 2; fr++) {
                const int rloc = wm * 32 + mtl * 16 + qr + fr * 8;
                const int grow = mt * 128 + rloc;
                const float yy = dec0W ? __ldcg(&g_y[grow]) : 0.f;
#pragma unroll
                for (int n8 = 0; n8 < 2; n8++) {
#pragma unroll
                    for (int e = 0; e < 2; e++) {
                        const int jl = wn * 16 + n8 * 8 + qc * 2 + e;
                        const int j = nt * 32 + jl;
                        const int ci = fr * 2 + e;
                        float rv = aR[mtl][n8][ci] * INVWS;
                        float zv = aZ[mtl][n8][ci] * INVWS;
                        float nh = aNH[mtl][n8][ci] * INVWS;
                        float ni;
                        if (dec0W) {
                            rv += yy * dec0W[j];
                            zv += yy * dec0W[HD + j];
                            ni  = yy * dec0W[2 * HD + j];
                        } else {
                            ni = aNI[mtl][n8][ci] * INVWS;
                        }
                        const float r = 1.f / (1.f + __expf(-(rv + g_br[bt][j])));
                        const float z = 1.f / (1.f + __expf(-(zv + g_bz[bt][j])));
                        const float n = tanhf(ni + g_bin[bt][j] + r * (nh + g_bhn[bt][j]));
                        const float hp = hprev[(size_t)grow * HD + j];
                        const float hv = n + z * (hp - n);
                        hout[(size_t)grow * HD + j] = hv;
                        hq[offel(rloc, kbase + jl)] = __float2half(hv);
                    }
                }
            }
        }
    };

    // chunk-list builders
    Ck ckL0[9], ckA[8], ckB[8];
    auto buildL0enc = [&](int t, int par, Ck* o) {
        for (int c = 0; c < 8; c++) o[c] = { &g_h1h[par][mt][c][0], &g_w[0][nt][c][0], 0 };
        o[8] = { &g_xh[t][mt][0], &g_wx[nt][0], 1 };
    };
    auto buildL0dec = [&](int par, Ck* o) {
        for (int c = 0; c < 8; c++) o[c] = { &g_h1h[par][mt][c][0], &g_w[3][nt][c][0], 0 };
    };

    int p = 0, st = 0;

    // prefetch first encoder l0
    buildL0enc(0, 0, ckL0);
    load2(ckL0);

    // ---------------- encoder: 512 steps ----------------
    for (int t = 0; t < TSEQ; t++) {
        zero_acc();
        run_seg_pre(ckL0, 9);                      // reads h1h[p], xh[t]
        if (st > 0) waitph(2 * st - 1);            // b_{st-1}: h2h[p] ready
        for (int c = 0; c < 8; c++) {
            ckA[c] = { &g_h2h[p][mt][c][0], &g_w[2][nt][c][0], 0 };
            ckB[c] = { &g_h1h[1 - p][mt][c][0], &g_w[1][nt][c][0], 1 };
        }
        load2(ckA);                                // l1-hidden prefetch (h2h[p] safe)
        epilogue(0, g_h1[p], g_h1[1 - p], &g_h1h[1 - p][mt][nt >> 1][0], nullptr);
        arriveph(2 * st);                          // a_st: h1 ready
        zero_acc();
        run_l1(ckA, ckB, 2 * st);                  // 16 chunks; wait(a) inside
        // prefetch next step's l0 (h1h[1-p] safe: passed wait(a) inside run_l1)
        if (t + 1 < TSEQ) buildL0enc(t + 1, 1 - p, ckL0);
        else              buildL0dec(1 - p, ckL0);
        load2(ckL0);
        epilogue(1, g_h2[p], g_h2[1 - p], &g_h2h[1 - p][mt][nt >> 1][0], nullptr);
        arriveph(2 * st + 1);                      // b_st: h2 ready
        p ^= 1; st++;
    }

    // ---------------- decoder: 96 steps ----------------
    for (int s = 0; s < PLEN; s++) {
        zero_acc();
        run_seg_pre(ckL0, 8);                      // reads h1h[p]
        waitph(2 * st - 1);                        // b_{st-1}: g_y + h2h[p] ready
        for (int c = 0; c < 8; c++) {
            ckA[c] = { &g_h2h[p][mt][c][0], &g_w[5][nt][c][0], 0 };
            ckB[c] = { &g_h1h[1 - p][mt][c][0], &g_w[4][nt][c][0], 1 };
        }
        load2(ckA);
        epilogue(2, g_h1[p], g_h1[1 - p], &g_h1h[1 - p][mt][nt >> 1][0], dWih0);
        arriveph(2 * st);
        zero_acc();
        run_l1(ckA, ckB, 2 * st);
        // prefetch next decoder l0 (safe: passed wait(a))
        if (s + 1 < PLEN) { buildL0dec(1 - p, ckL0); load2(ckL0); }
        epilogue(3, g_h2[p], g_h2[1 - p], &g_h2h[1 - p][mt][nt >> 1][0], nullptr);
        gbar();                                    // full: projection reads fp32 h2 cross-CTA
        {
            const int row = blockIdx.x * 8 + wid;
            const float* hr = g_h2[1 - p] + (size_t)row * HD;
            float ss = 0.f;
#pragma unroll
            for (int q = 0; q < HD / 32; q++)
                ss += __ldcg(&hr[lane + 32 * q]) * outW[lane + 32 * q];
#pragma unroll
            for (int o = 16; o > 0; o >>= 1)
                ss += __shfl_xor_sync(0xffffffffu, ss, o);
            if (lane == 0) {
                const float v = ss + outb[0];
                g_y[row] = v;
                out[(size_t)row * PLEN + s] = v;
            }
        }
        arriveph(2 * st + 1);                      // b_st: g_y + h2h ready
        p ^= 1; st++;
    }
}

// ---------------------------------------------------------------------------
extern "C" void kernel_launch(void* const* d_in, const int* in_sizes, int n_in,
                              void* d_out, int out_size)
{
    const float* x      = (const float*)d_in[0];
    const float* eWih0  = (const float*)d_in[1];
    const float* eWhh0  = (const float*)d_in[2];
    const float* ebih0  = (const float*)d_in[3];
    const float* ebhh0  = (const float*)d_in[4];
    const float* eWih1  = (const float*)d_in[5];
    const float* eWhh1  = (const float*)d_in[6];
    const float* ebih1  = (const float*)d_in[7];
    const float* ebhh1  = (const float*)d_in[8];
    const float* dWih0  = (const float*)d_in[9];
    const float* dWhh0  = (const float*)d_in[10];
    const float* dbih0  = (const float*)d_in[11];
    const float* dbhh0  = (const float*)d_in[12];
    const float* dWih1  = (const float*)d_in[13];
    const float* dWhh1  = (const float*)d_in[14];
    const float* dbih1  = (const float*)d_in[15];
    const float* dbhh1  = (const float*)d_in[16];
    const float* outW   = (const float*)d_in[17];
    const float* outb   = (const float*)d_in[18];
    const float* dstart = (const float*)d_in[19];
    float* out = (float*)d_out;

    cudaFuncSetAttribute(gru_tc, cudaFuncAttributeMaxDynamicSharedMemorySize, SM_TOTAL);

    init_weights<<<1024, 256>>>(eWih0,
                                eWhh0, eWih1, eWhh1, dWhh0, dWih1, dWhh1,
                                ebih0, ebhh0, ebih1, ebhh1,
                                dbih0, dbhh0, dbih1, dbhh1);
    init_x<<<2048, 256>>>(x);
    gru_tc<<<NCTA, 256, SM_TOTAL>>>(dWih0, outW, outb, dstart, out);
}